// round 12
// baseline (speedup 1.0000x reference)
#include <cuda_runtime.h>
#include <cuda_bf16.h>

#define NP   4096
#define KNN  32
#define CIN  16
#define COUT 32
#define NB   27
#define NG   432
#define QB   8        // queries per knn block
#define SCAP 384      // survivor cap per query

__device__ float4 g_posq[NP];
__device__ int    g_nbr[NP * KNN];
__device__ float  g_coefT[108 * 128];     // [j/4][o][j%4]
__device__ float4 g_frame[NP * 3];        // (cx,cy,cz,V00),(V01,V02,V10,V11),(V12,V20,V21,V22)
__device__ float  g_cscratch[NP * 3];
__device__ float  g_oscratch[NP * COUT];

// ---------------------------------------------------------------------------
// LAPACK fp32 helpers (LAPACK >= 3.10 conventions) — validated R2..R10
// ---------------------------------------------------------------------------
__device__ __forceinline__ float slapy2f(float x, float y) {
    float xa = fabsf(x), ya = fabsf(y);
    float w = fmaxf(xa, ya), z = fminf(xa, ya);
    if (z == 0.f) return w;
    float t = z / w;
    return w * sqrtf(1.f + t * t);
}

__device__ __forceinline__ void slartgf(float f, float g, float* c, float* s, float* r) {
    if (g == 0.f)      { *c = 1.f; *s = 0.f; *r = f; }
    else if (f == 0.f) { *c = 0.f; *s = (g > 0.f) ? 1.f : -1.f; *r = fabsf(g); }
    else {
        float d = sqrtf(f * f + g * g);
        float p = 1.f / d;
        *c = fabsf(f) * p;
        *s = g * copysignf(p, f);
        *r = copysignf(d, f);
    }
}

__device__ void slaev2f(float a, float b, float c, float* rt1, float* rt2,
                        float* cs1, float* sn1) {
    float sm = a + c, df = a - c;
    float adf = fabsf(df);
    float tb = b + b, ab = fabsf(tb);
    float acmx, acmn;
    if (fabsf(a) > fabsf(c)) { acmx = a; acmn = c; } else { acmx = c; acmn = a; }
    float rt;
    if (adf > ab)      { float t = ab / adf; rt = adf * sqrtf(1.f + t * t); }
    else if (adf < ab) { float t = adf / ab; rt = ab * sqrtf(1.f + t * t); }
    else               rt = ab * sqrtf(2.f);
    int sgn1;
    if (sm < 0.f)      { *rt1 = 0.5f * (sm - rt); sgn1 = -1;
                         *rt2 = (acmx / *rt1) * acmn - (b / *rt1) * b; }
    else if (sm > 0.f) { *rt1 = 0.5f * (sm + rt); sgn1 = 1;
                         *rt2 = (acmx / *rt1) * acmn - (b / *rt1) * b; }
    else               { *rt1 = 0.5f * rt; *rt2 = -0.5f * rt; sgn1 = 1; }
    float cs; int sgn2;
    if (df >= 0.f) { cs = df + rt; sgn2 = 1; } else { cs = df - rt; sgn2 = -1; }
    float acs = fabsf(cs);
    if (acs > ab) {
        float ct = -tb / cs;
        *sn1 = 1.f / sqrtf(1.f + ct * ct);
        *cs1 = ct * *sn1;
    } else {
        if (ab == 0.f) { *cs1 = 1.f; *sn1 = 0.f; }
        else {
            float tn = -cs / tb;
            *cs1 = 1.f / sqrtf(1.f + tn * tn);
            *sn1 = tn * *cs1;
        }
    }
    if (sgn1 == sgn2) { float tn = *cs1; *cs1 = -*sn1; *sn1 = tn; }
}

__device__ void ssteqr3(float* D, float* E, float z[3][3]) {
    const float eps = 5.9604645e-08f, eps2 = eps * eps, safmin = 1.17549435e-38f;
    const int n = 3, nmaxit = 90;
    float d[4] = {0.f, D[0], D[1], D[2]};
    float e[3] = {0.f, E[0], E[1]};
    for (int i = 0; i < 3; ++i)
        for (int j = 0; j < 3; ++j) z[i][j] = (i == j) ? 1.f : 0.f;
    int jtot = 0, l1 = 1;
    float wc[3], ws[3];

    while (l1 <= n) {
        if (l1 > 1) e[l1 - 1] = 0.f;
        int m = n;
        for (int mm = l1; mm <= n - 1; ++mm) {
            float tst = fabsf(e[mm]);
            if (tst == 0.f) { m = mm; break; }
            if (tst <= (sqrtf(fabsf(d[mm])) * sqrtf(fabsf(d[mm + 1]))) * eps) {
                e[mm] = 0.f; m = mm; break;
            }
        }
        int l = l1;
        int lsv = l, lend = m, lendsv = lend;
        l1 = m + 1;
        if (lend == l) continue;
        if (fabsf(d[lend]) < fabsf(d[l])) { lend = lsv; l = lendsv; }

        if (lend > l) {
            for (;;) {
                int mq = lend;
                if (l != lend) {
                    for (int mi = l; mi <= lend - 1; ++mi) {
                        float tst = e[mi] * e[mi];
                        if (tst <= (eps2 * fabsf(d[mi])) * fabsf(d[mi + 1]) + safmin) {
                            mq = mi; break;
                        }
                    }
                }
                if (mq < lend) e[mq] = 0.f;
                float p = d[l];
                if (mq == l) { d[l] = p; if (++l <= lend) continue; break; }
                if (mq == l + 1) {
                    float rt1, rt2, c, s;
                    slaev2f(d[l], e[l], d[l + 1], &rt1, &rt2, &c, &s);
                    for (int i = 0; i < 3; ++i) {
                        float t = z[i][l];
                        z[i][l]     = c * t - s * z[i][l - 1];
                        z[i][l - 1] = s * t + c * z[i][l - 1];
                    }
                    d[l] = rt1; d[l + 1] = rt2; e[l] = 0.f;
                    l += 2;
                    if (l <= lend) continue;
                    break;
                }
                if (jtot == nmaxit) break;
                ++jtot;
                float g = (d[l + 1] - p) / (2.f * e[l]);
                float r = slapy2f(g, 1.f);
                g = d[mq] - p + (e[l] / (g + copysignf(r, g)));
                float s = 1.f, c = 1.f; p = 0.f;
                for (int i = mq - 1; i >= l; --i) {
                    float f = s * e[i], b = c * e[i];
                    slartgf(g, f, &c, &s, &r);
                    if (i != mq - 1) e[i + 1] = r;
                    g = d[i + 1] - p;
                    r = (d[i] - g) * s + 2.f * c * b;
                    p = s * r;
                    d[i + 1] = g + p;
                    g = c * r - b;
                    wc[i] = c; ws[i] = -s;
                }
                for (int j = mq - l; j >= 1; --j) {
                    float ct = wc[l + j - 1], st = ws[l + j - 1];
                    for (int i = 0; i < 3; ++i) {
                        float t = z[i][l + j - 1];
                        z[i][l + j - 1] = ct * t - st * z[i][l + j - 2];
                        z[i][l + j - 2] = st * t + ct * z[i][l + j - 2];
                    }
                }
                d[l] -= p;
                e[l] = g;
            }
        } else {
            for (;;) {
                int mq = lend;
                if (l != lend) {
                    for (int mi = l; mi >= lend + 1; --mi) {
                        float tst = e[mi - 1] * e[mi - 1];
                        if (tst <= (eps2 * fabsf(d[mi])) * fabsf(d[mi - 1]) + safmin) {
                            mq = mi; break;
                        }
                    }
                }
                if (mq > lend) e[mq - 1] = 0.f;
                float p = d[l];
                if (mq == l) { d[l] = p; if (--l >= lend) continue; break; }
                if (mq == l - 1) {
                    float rt1, rt2, c, s;
                    slaev2f(d[l - 1], e[l - 1], d[l], &rt1, &rt2, &c, &s);
                    for (int i = 0; i < 3; ++i) {
                        float t = z[i][l - 1];
                        z[i][l - 1] = c * t - s * z[i][l - 2];
                        z[i][l - 2] = s * t + c * z[i][l - 2];
                    }
                    d[l - 1] = rt1; d[l] = rt2; e[l - 1] = 0.f;
                    l -= 2;
                    if (l >= lend) continue;
                    break;
                }
                if (jtot == nmaxit) break;
                ++jtot;
                float g = (d[l - 1] - p) / (2.f * e[l - 1]);
                float r = slapy2f(g, 1.f);
                g = d[mq] - p + (e[l - 1] / (g + copysignf(r, g)));
                float s = 1.f, c = 1.f; p = 0.f;
                for (int i = mq; i <= l - 1; ++i) {
                    float f = s * e[i], b = c * e[i];
                    slartgf(g, f, &c, &s, &r);
                    if (i != mq) e[i - 1] = r;
                    g = d[i] - p;
                    r = (d[i + 1] - g) * s + 2.f * c * b;
                    p = s * r;
                    d[i] = g + p;
                    g = c * r - b;
                    wc[i] = c; ws[i] = s;
                }
                for (int j = 1; j <= l - mq; ++j) {
                    float ct = wc[mq + j - 1], st = ws[mq + j - 1];
                    for (int i = 0; i < 3; ++i) {
                        float t = z[i][mq + j - 1];
                        z[i][mq + j - 1] = ct * t - st * z[i][mq + j - 2];
                        z[i][mq + j - 2] = st * t + ct * z[i][mq + j - 2];
                    }
                }
                d[l] -= p;
                e[l - 1] = g;
            }
        }
    }
    for (int ii = 2; ii <= n; ++ii) {
        int i = ii - 1, k = i;
        float p = d[i];
        for (int j = ii; j <= n; ++j) if (d[j] < p) { k = j; p = d[j]; }
        if (k != i) {
            d[k] = d[i]; d[i] = p;
            for (int r2 = 0; r2 < 3; ++r2) {
                float t = z[r2][i - 1]; z[r2][i - 1] = z[r2][k - 1]; z[r2][k - 1] = t;
            }
        }
    }
}

__device__ void eigh3(const float A[6], float V[3][3]) {
    float a00 = A[0], a10 = A[1], a20 = A[2], a11 = A[3], a21 = A[4], a22 = A[5];
    float tau = 0.f, v2 = 0.f, e0, e1, d1 = a11, d2v = a22;
    float xnorm = fabsf(a20);
    if (xnorm == 0.f) { tau = 0.f; e0 = a10; e1 = a21; }
    else {
        float alpha = a10;
        float beta = -copysignf(slapy2f(alpha, xnorm), alpha);
        tau = (beta - alpha) / beta;
        v2 = a20 * (1.f / (alpha - beta));
        e0 = beta;
        float w0 = tau * a11 + tau * (a21 * v2);
        float w1 = tau * a21 + (tau * v2) * a22;
        float aw = -0.5f * tau * (w0 + w1 * v2);
        w0 += aw; w1 += aw * v2;
        d1  = (a11 - w0) - w0;
        e1  = (a21 - v2 * w0) - w1;
        d2v = (a22 - v2 * w1) - w1 * v2;
    }
    float d[3] = {a00, d1, d2v};
    float e[2] = {e0, e1};
    ssteqr3(d, e, V);
    if (tau != 0.f) {
        for (int j = 0; j < 3; ++j) {
            float s = V[1][j] + v2 * V[2][j];
            V[1][j] -= tau * s;
            V[2][j] -= tau * v2 * s;
        }
    }
}

// ---------------------------------------------------------------------------
__device__ __forceinline__ unsigned long long warp_min64(unsigned long long k) {
    unsigned hi = (unsigned)(k >> 32), lo = (unsigned)k;
    unsigned mhi = __reduce_min_sync(0xffffffffu, hi);
    unsigned lo2 = (hi == mhi) ? lo : 0xffffffffu;
    unsigned mlo = __reduce_min_sync(0xffffffffu, lo2);
    return ((unsigned long long)mhi << 32) | mlo;
}

__device__ __forceinline__ unsigned f2u(float f) {
    int i = __float_as_int(f);
    return (i < 0) ? ~(unsigned)i : ((unsigned)i | 0x80000000u);
}

// prep + coef transpose fused into one launch
__global__ void setup_kernel(const float* __restrict__ pos,
                             const float* __restrict__ coef) {
    int i = blockIdx.x * blockDim.x + threadIdx.x;
    if (i < NP) {
        float x = pos[3 * i], y = pos[3 * i + 1], z = pos[3 * i + 2];
        g_posq[i] = make_float4(x, y, z, x * x + y * y + z * z);
    }
    if (i < COUT * NG) {
        int o = i / NG, j = i - o * NG;
        g_coefT[(j >> 2) * 128 + o * 4 + (j & 3)] = coef[i];
    }
}

// ---------------------------------------------------------------------------
// Kernel 1: exact kNN, 8 queries per block (validated R5/R6/R10 version)
// ---------------------------------------------------------------------------
__global__ __launch_bounds__(256)
void knn_kernel() {
    const int tid = threadIdx.x;
    const int lane = tid & 31;
    const int wid = tid >> 5;
    const int qbase = blockIdx.x * QB;

    __shared__ unsigned long long s_surv[QB][SCAP];
    __shared__ unsigned s_b4[QB][8];
    __shared__ int s_cnt[QB];

    if (tid < QB) s_cnt[tid] = 0;

    float4 pq[QB];
#pragma unroll
    for (int q = 0; q < QB; ++q) pq[q] = g_posq[qbase + q];

    float mn[QB];
#pragma unroll
    for (int q = 0; q < QB; ++q) mn[q] = __int_as_float(0x7f800000);

#pragma unroll 4
    for (int j = 0; j < 16; ++j) {
        int cand = tid + (j << 8);
        float4 cq = g_posq[cand];
#pragma unroll
        for (int q = 0; q < QB; ++q) {
            float dot = pq[q].x * cq.x + pq[q].y * cq.y + pq[q].z * cq.z;
            float d2 = (pq[q].w + cq.w) - 2.f * dot;
            mn[q] = fminf(mn[q], d2);
        }
    }

#pragma unroll
    for (int q = 0; q < QB; ++q) {
        unsigned h = f2u(mn[q]), w4 = 0;
#pragma unroll
        for (int r = 0; r < 4; ++r) {
            w4 = __reduce_min_sync(0xffffffffu, h);
            if (h == w4) h = 0xffffffffu;
        }
        if (lane == 0) s_b4[q][wid] = w4;
    }
    __syncthreads();

    float Bf[QB];
#pragma unroll
    for (int q = 0; q < QB; ++q) {
        unsigned B = s_b4[q][0];
#pragma unroll
        for (int w = 1; w < 8; ++w) B = max(B, s_b4[q][w]);
        int bi = (B & 0x80000000u) ? (int)(B & 0x7fffffffu) : (int)~B;
        Bf[q] = __int_as_float(bi);
    }

#pragma unroll
    for (int q = 0; q < QB; ++q) {
        if (mn[q] <= Bf[q]) {
#pragma unroll 4
            for (int j = 0; j < 16; ++j) {
                int cand = tid + (j << 8);
                float4 cq = g_posq[cand];
                float dot = pq[q].x * cq.x + pq[q].y * cq.y + pq[q].z * cq.z;
                float d2 = (pq[q].w + cq.w) - 2.f * dot;
                if (d2 <= Bf[q]) {
                    unsigned u = f2u(d2);
                    int pos = atomicAdd(&s_cnt[q], 1);
                    if (pos < SCAP)
                        s_surv[q][pos] = ((unsigned long long)u << 32) | (unsigned)cand;
                }
            }
        }
    }
    __syncthreads();

    {
        const int q = wid;
        int S = s_cnt[q] < SCAP ? s_cnt[q] : SCAP;
        for (int r = 0; r < KNN; ++r) {
            unsigned long long m = ~0ULL; int mi = -1;
            for (int i = lane; i < S; i += 32) {
                unsigned long long v = s_surv[q][i];
                if (v < m) { m = v; mi = i; }
            }
            unsigned long long w = warp_min64(m);
            if (m == w && mi >= 0) s_surv[q][mi] = ~0ULL;
            if (lane == 0) g_nbr[(qbase + q) * KNN + r] = (int)(w & 0xffffffffu);
        }
    }
}

// ---------------------------------------------------------------------------
// Kernel 2: frames — one warp per point (validated R10, ~15us)
// ---------------------------------------------------------------------------
__global__ __launch_bounds__(128)
void frame_kernel(float* __restrict__ centers_out) {
    const int tid = threadIdx.x;
    const int lane = tid & 31;
    const int wid = tid >> 5;
    const int p = blockIdx.x * 4 + wid;

    const int nb = g_nbr[p * KNN + lane];
    const float4 q = g_posq[nb];

    float cx = q.x, cy = q.y, cz = q.z;
#pragma unroll
    for (int off = 16; off; off >>= 1) {
        cx += __shfl_xor_sync(0xffffffffu, cx, off);
        cy += __shfl_xor_sync(0xffffffffu, cy, off);
        cz += __shfl_xor_sync(0xffffffffu, cz, off);
    }
    cx *= 0.03125f; cy *= 0.03125f; cz *= 0.03125f;
    if (lane == 0) {
        centers_out[3 * p]     = cx;
        centers_out[3 * p + 1] = cy;
        centers_out[3 * p + 2] = cz;
    }

    const float lx = q.x - cx, ly = q.y - cy, lz = q.z - cz;
    float c00 = lx * lx, c01 = lx * ly, c02 = lx * lz;
    float c11 = ly * ly, c12 = ly * lz, c22 = lz * lz;
#pragma unroll
    for (int off = 16; off; off >>= 1) {
        c00 += __shfl_xor_sync(0xffffffffu, c00, off);
        c01 += __shfl_xor_sync(0xffffffffu, c01, off);
        c02 += __shfl_xor_sync(0xffffffffu, c02, off);
        c11 += __shfl_xor_sync(0xffffffffu, c11, off);
        c12 += __shfl_xor_sync(0xffffffffu, c12, off);
        c22 += __shfl_xor_sync(0xffffffffu, c22, off);
    }
    if (lane == 0) {
        float A[6] = {c00 * 0.03125f, c01 * 0.03125f, c02 * 0.03125f,
                      c11 * 0.03125f, c12 * 0.03125f, c22 * 0.03125f};
        float V[3][3];
        eigh3(A, V);
        g_frame[p * 3 + 0] = make_float4(cx, cy, cz, V[0][0]);
        g_frame[p * 3 + 1] = make_float4(V[0][1], V[0][2], V[1][0], V[1][1]);
        g_frame[p * 3 + 2] = make_float4(V[1][2], V[2][0], V[2][1], V[2][2]);
    }
}

// ---------------------------------------------------------------------------
// Kernel 3: conv — TWO warps per point (frames precomputed, so no duplicated
// eigh/cov: R6's failure mode is gone). Phase4/5 split orders == R6 (passed).
// ---------------------------------------------------------------------------
__global__ __launch_bounds__(256)
void conv_kernel(const float* __restrict__ chan,
                 float* __restrict__ out) {
    const int tid  = threadIdx.x;
    const int lane = tid & 31;
    const int wid  = tid >> 5;          // 0..7
    const int pt   = wid >> 1;          // 0..3
    const int sub  = wid & 1;
    const int p = blockIdx.x * 4 + pt;

    __shared__ float s_basis[4][2][16][28];  // [pt][sub][krow][basis+pad]
    __shared__ float s_feat[4][2][16][16];
    __shared__ float s_Gp[4][2][448];
    __shared__ float s_po[4][2][32];

    // frame (broadcast loads)
    const float4 f0 = __ldg(&g_frame[p * 3 + 0]);
    const float4 f1 = __ldg(&g_frame[p * 3 + 1]);
    const float4 f2 = __ldg(&g_frame[p * 3 + 2]);
    const float cx = f0.x, cy = f0.y, cz = f0.z;
    const float v00 = f0.w, v01 = f1.x, v02 = f1.y;
    const float v10 = f1.z, v11 = f1.w, v12 = f2.x;
    const float v20 = f2.y, v21 = f2.z, v22 = f2.w;

    // features for this warp's 16 k-rows: lane -> (krow = lane>>1, h8 = lane&1)
    {
        int krow = lane >> 1;
        int nbf = g_nbr[p * KNN + sub * 16 + krow];
        const float4* fr = (const float4*)(chan + nbf * CIN);
        int h8 = lane & 1;
        float4 fa = fr[h8 * 2], fb = fr[h8 * 2 + 1];
        float4* sf = (float4*)&s_feat[pt][sub][krow][h8 * 8];
        sf[0] = fa; sf[1] = fb;
    }

    // basis for this warp's 16 k-rows (lanes 0..15)
    {
        int krow = lane & 15;
        int nb16 = g_nbr[p * KNN + sub * 16 + krow];
        float4 q = g_posq[nb16];
        if (lane < 16) {
            float lx = q.x - cx, ly = q.y - cy, lz = q.z - cz;
            float x = lx * v00 + ly * v10 + lz * v20;
            float y = lx * v01 + ly * v11 + lz * v21;
            float z = lx * v02 + ly * v12 + lz * v22;
            float r = sqrtf(x * x + y * y + z * z);
            float ct = z / (r + 1e-8f);
            ct = fminf(fmaxf(ct, -1.f + 1e-6f), 1.f - 1e-6f);
            float theta = acosf(ct);
            float phi = atan2f(y, x);
            float rb[3] = {1.f, r, r * r};
            float tb[3] = {1.f, cosf(theta), cosf(2.f * theta)};
            float pb[3] = {1.f, cosf(phi), cosf(2.f * phi)};
#pragma unroll
            for (int n = 0; n < 3; ++n)
#pragma unroll
                for (int l = 0; l < 3; ++l)
#pragma unroll
                    for (int m = 0; m < 3; ++m)
                        s_basis[pt][sub][krow][n * 9 + l * 3 + m] = (rb[n] * tb[l]) * pb[m];
            s_basis[pt][sub][krow][27] = 0.f;
        }
    }
    __syncthreads();

    // phase 4 (split): partial G over this warp's 16 k's (order == R6, passed)
    {
        const int c = lane >> 1;
        const int half = lane & 1;
        float acc[16];
#pragma unroll
        for (int i = 0; i < 16; ++i) acc[i] = 0.f;

#pragma unroll 8
        for (int k = 0; k < 16; ++k) {
            float fv = s_feat[pt][sub][k][c];
            const float* row = &s_basis[pt][sub][k][0];
            if (half == 0) {
                float4 b0 = *(const float4*)(row);
                float4 b1 = *(const float4*)(row + 4);
                float4 b2 = *(const float4*)(row + 8);
                float4 b3 = *(const float4*)(row + 12);
                acc[0]  += b0.x * fv; acc[1]  += b0.y * fv; acc[2]  += b0.z * fv; acc[3]  += b0.w * fv;
                acc[4]  += b1.x * fv; acc[5]  += b1.y * fv; acc[6]  += b1.z * fv; acc[7]  += b1.w * fv;
                acc[8]  += b2.x * fv; acc[9]  += b2.y * fv; acc[10] += b2.z * fv; acc[11] += b2.w * fv;
                acc[12] += b3.x * fv; acc[13] += b3.y * fv; acc[14] += b3.z * fv; acc[15] += b3.w * fv;
            } else {
                float4 b0 = *(const float4*)(row + 16);
                float4 b1 = *(const float4*)(row + 20);
                float4 b2 = *(const float4*)(row + 24);
                acc[0]  += b0.x * fv; acc[1]  += b0.y * fv; acc[2]  += b0.z * fv; acc[3]  += b0.w * fv;
                acc[4]  += b1.x * fv; acc[5]  += b1.y * fv; acc[6]  += b1.z * fv; acc[7]  += b1.w * fv;
                acc[8]  += b2.x * fv; acc[9]  += b2.y * fv; acc[10] += b2.z * fv;
            }
        }
        float* Gp = &s_Gp[pt][sub][0];
        if (half == 0) {
#pragma unroll
            for (int i = 0; i < 16; ++i) Gp[c * 27 + i] = acc[i];
        } else {
#pragma unroll
            for (int i = 0; i < 11; ++i) Gp[c * 27 + 16 + i] = acc[i];
        }
        if (lane < 16) Gp[432 + lane] = 0.f;     // pad for float4 reads
    }
    __syncthreads();

    // phase 5 (split): out partial over this warp's 54 t's (order == R6)
    {
        float a0 = 0.f, a1 = 0.f, a2 = 0.f, a3 = 0.f;
        const float* gT = g_coefT + lane * 4 + sub * 54 * 128;
        const float* g0 = &s_Gp[pt][0][sub * 54 * 4];
        const float* g1 = &s_Gp[pt][1][sub * 54 * 4];
#pragma unroll 3
        for (int t = 0; t < 54; ++t) {
            float4 cf = *(const float4*)(gT + t * 128);
            float4 ga = *(const float4*)(g0 + t * 4);
            float4 gb = *(const float4*)(g1 + t * 4);
            a0 += cf.x * (ga.x + gb.x);
            a1 += cf.y * (ga.y + gb.y);
            a2 += cf.z * (ga.z + gb.z);
            a3 += cf.w * (ga.w + gb.w);
        }
        s_po[pt][sub][lane] = (a0 + a1) + (a2 + a3);
    }
    __syncthreads();

    if (sub == 0)
        out[p * COUT + lane] = s_po[pt][0][lane] + s_po[pt][1][lane];
}

extern "C" void kernel_launch(void* const* d_in, const int* in_sizes, int n_in,
                              void* d_out, int out_size) {
    const float* pos  = (const float*)d_in[0];
    const float* chan = (const float*)d_in[1];
    const float* coef = (const float*)d_in[3];

    float* d_outf = (float*)d_out;
    float* centers_ptr;
    float* out_ptr;
    if (out_size == NP * 3 + NP * COUT) {
        centers_ptr = d_outf;
        out_ptr     = d_outf + NP * 3;
    } else if (out_size == NP * COUT) {
        cudaGetSymbolAddress((void**)&centers_ptr, g_cscratch);
        out_ptr = d_outf;
    } else {
        centers_ptr = d_outf;
        cudaGetSymbolAddress((void**)&out_ptr, g_oscratch);
    }

    setup_kernel<<<108, 128>>>(pos, coef);
    knn_kernel<<<NP / QB, 256>>>();
    frame_kernel<<<NP / 4, 128>>>(centers_ptr);
    conv_kernel<<<NP / 4, 256>>>(chan, out_ptr);
}

// round 13
// speedup vs baseline: 1.1364x; 1.1364x over previous
#include <cuda_runtime.h>
#include <cuda_bf16.h>

#define NP   4096
#define KNN  32
#define CIN  16
#define COUT 32
#define NB   27
#define NG   432
#define QB   8        // queries per knn block
#define SCAP 384      // survivor cap per query

__device__ float4 g_posq[NP];
__device__ int    g_nbr[NP * KNN];
__device__ float  g_coefT[108 * 128];     // [j/4][o][j%4]
__device__ float4 g_frame[NP * 3];        // (cx,cy,cz,V00),(V01,V02,V10,V11),(V12,V20,V21,V22)
__device__ float  g_cscratch[NP * 3];
__device__ float  g_oscratch[NP * COUT];

// ---------------------------------------------------------------------------
// LAPACK fp32 helpers (LAPACK >= 3.10 conventions) — validated R2..R11
// ---------------------------------------------------------------------------
__device__ __forceinline__ float slapy2f(float x, float y) {
    float xa = fabsf(x), ya = fabsf(y);
    float w = fmaxf(xa, ya), z = fminf(xa, ya);
    if (z == 0.f) return w;
    float t = z / w;
    return w * sqrtf(1.f + t * t);
}

__device__ __forceinline__ void slartgf(float f, float g, float* c, float* s, float* r) {
    if (g == 0.f)      { *c = 1.f; *s = 0.f; *r = f; }
    else if (f == 0.f) { *c = 0.f; *s = (g > 0.f) ? 1.f : -1.f; *r = fabsf(g); }
    else {
        float d = sqrtf(f * f + g * g);
        float p = 1.f / d;
        *c = fabsf(f) * p;
        *s = g * copysignf(p, f);
        *r = copysignf(d, f);
    }
}

__device__ void slaev2f(float a, float b, float c, float* rt1, float* rt2,
                        float* cs1, float* sn1) {
    float sm = a + c, df = a - c;
    float adf = fabsf(df);
    float tb = b + b, ab = fabsf(tb);
    float acmx, acmn;
    if (fabsf(a) > fabsf(c)) { acmx = a; acmn = c; } else { acmx = c; acmn = a; }
    float rt;
    if (adf > ab)      { float t = ab / adf; rt = adf * sqrtf(1.f + t * t); }
    else if (adf < ab) { float t = adf / ab; rt = ab * sqrtf(1.f + t * t); }
    else               rt = ab * sqrtf(2.f);
    int sgn1;
    if (sm < 0.f)      { *rt1 = 0.5f * (sm - rt); sgn1 = -1;
                         *rt2 = (acmx / *rt1) * acmn - (b / *rt1) * b; }
    else if (sm > 0.f) { *rt1 = 0.5f * (sm + rt); sgn1 = 1;
                         *rt2 = (acmx / *rt1) * acmn - (b / *rt1) * b; }
    else               { *rt1 = 0.5f * rt; *rt2 = -0.5f * rt; sgn1 = 1; }
    float cs; int sgn2;
    if (df >= 0.f) { cs = df + rt; sgn2 = 1; } else { cs = df - rt; sgn2 = -1; }
    float acs = fabsf(cs);
    if (acs > ab) {
        float ct = -tb / cs;
        *sn1 = 1.f / sqrtf(1.f + ct * ct);
        *cs1 = ct * *sn1;
    } else {
        if (ab == 0.f) { *cs1 = 1.f; *sn1 = 0.f; }
        else {
            float tn = -cs / tb;
            *cs1 = 1.f / sqrtf(1.f + tn * tn);
            *sn1 = tn * *cs1;
        }
    }
    if (sgn1 == sgn2) { float tn = *cs1; *cs1 = -*sn1; *sn1 = tn; }
}

__device__ void ssteqr3(float* D, float* E, float z[3][3]) {
    const float eps = 5.9604645e-08f, eps2 = eps * eps, safmin = 1.17549435e-38f;
    const int n = 3, nmaxit = 90;
    float d[4] = {0.f, D[0], D[1], D[2]};
    float e[3] = {0.f, E[0], E[1]};
    for (int i = 0; i < 3; ++i)
        for (int j = 0; j < 3; ++j) z[i][j] = (i == j) ? 1.f : 0.f;
    int jtot = 0, l1 = 1;
    float wc[3], ws[3];

    while (l1 <= n) {
        if (l1 > 1) e[l1 - 1] = 0.f;
        int m = n;
        for (int mm = l1; mm <= n - 1; ++mm) {
            float tst = fabsf(e[mm]);
            if (tst == 0.f) { m = mm; break; }
            if (tst <= (sqrtf(fabsf(d[mm])) * sqrtf(fabsf(d[mm + 1]))) * eps) {
                e[mm] = 0.f; m = mm; break;
            }
        }
        int l = l1;
        int lsv = l, lend = m, lendsv = lend;
        l1 = m + 1;
        if (lend == l) continue;
        if (fabsf(d[lend]) < fabsf(d[l])) { lend = lsv; l = lendsv; }

        if (lend > l) {
            for (;;) {
                int mq = lend;
                if (l != lend) {
                    for (int mi = l; mi <= lend - 1; ++mi) {
                        float tst = e[mi] * e[mi];
                        if (tst <= (eps2 * fabsf(d[mi])) * fabsf(d[mi + 1]) + safmin) {
                            mq = mi; break;
                        }
                    }
                }
                if (mq < lend) e[mq] = 0.f;
                float p = d[l];
                if (mq == l) { d[l] = p; if (++l <= lend) continue; break; }
                if (mq == l + 1) {
                    float rt1, rt2, c, s;
                    slaev2f(d[l], e[l], d[l + 1], &rt1, &rt2, &c, &s);
                    for (int i = 0; i < 3; ++i) {
                        float t = z[i][l];
                        z[i][l]     = c * t - s * z[i][l - 1];
                        z[i][l - 1] = s * t + c * z[i][l - 1];
                    }
                    d[l] = rt1; d[l + 1] = rt2; e[l] = 0.f;
                    l += 2;
                    if (l <= lend) continue;
                    break;
                }
                if (jtot == nmaxit) break;
                ++jtot;
                float g = (d[l + 1] - p) / (2.f * e[l]);
                float r = slapy2f(g, 1.f);
                g = d[mq] - p + (e[l] / (g + copysignf(r, g)));
                float s = 1.f, c = 1.f; p = 0.f;
                for (int i = mq - 1; i >= l; --i) {
                    float f = s * e[i], b = c * e[i];
                    slartgf(g, f, &c, &s, &r);
                    if (i != mq - 1) e[i + 1] = r;
                    g = d[i + 1] - p;
                    r = (d[i] - g) * s + 2.f * c * b;
                    p = s * r;
                    d[i + 1] = g + p;
                    g = c * r - b;
                    wc[i] = c; ws[i] = -s;
                }
                for (int j = mq - l; j >= 1; --j) {
                    float ct = wc[l + j - 1], st = ws[l + j - 1];
                    for (int i = 0; i < 3; ++i) {
                        float t = z[i][l + j - 1];
                        z[i][l + j - 1] = ct * t - st * z[i][l + j - 2];
                        z[i][l + j - 2] = st * t + ct * z[i][l + j - 2];
                    }
                }
                d[l] -= p;
                e[l] = g;
            }
        } else {
            for (;;) {
                int mq = lend;
                if (l != lend) {
                    for (int mi = l; mi >= lend + 1; --mi) {
                        float tst = e[mi - 1] * e[mi - 1];
                        if (tst <= (eps2 * fabsf(d[mi])) * fabsf(d[mi - 1]) + safmin) {
                            mq = mi; break;
                        }
                    }
                }
                if (mq > lend) e[mq - 1] = 0.f;
                float p = d[l];
                if (mq == l) { d[l] = p; if (--l >= lend) continue; break; }
                if (mq == l - 1) {
                    float rt1, rt2, c, s;
                    slaev2f(d[l - 1], e[l - 1], d[l], &rt1, &rt2, &c, &s);
                    for (int i = 0; i < 3; ++i) {
                        float t = z[i][l - 1];
                        z[i][l - 1] = c * t - s * z[i][l - 2];
                        z[i][l - 2] = s * t + c * z[i][l - 2];
                    }
                    d[l - 1] = rt1; d[l] = rt2; e[l - 1] = 0.f;
                    l -= 2;
                    if (l >= lend) continue;
                    break;
                }
                if (jtot == nmaxit) break;
                ++jtot;
                float g = (d[l - 1] - p) / (2.f * e[l - 1]);
                float r = slapy2f(g, 1.f);
                g = d[mq] - p + (e[l - 1] / (g + copysignf(r, g)));
                float s = 1.f, c = 1.f; p = 0.f;
                for (int i = mq; i <= l - 1; ++i) {
                    float f = s * e[i], b = c * e[i];
                    slartgf(g, f, &c, &s, &r);
                    if (i != mq) e[i - 1] = r;
                    g = d[i] - p;
                    r = (d[i + 1] - g) * s + 2.f * c * b;
                    p = s * r;
                    d[i] = g + p;
                    g = c * r - b;
                    wc[i] = c; ws[i] = s;
                }
                for (int j = 1; j <= l - mq; ++j) {
                    float ct = wc[mq + j - 1], st = ws[mq + j - 1];
                    for (int i = 0; i < 3; ++i) {
                        float t = z[i][mq + j - 1];
                        z[i][mq + j - 1] = ct * t - st * z[i][mq + j - 2];
                        z[i][mq + j - 2] = st * t + ct * z[i][mq + j - 2];
                    }
                }
                d[l] -= p;
                e[l - 1] = g;
            }
        }
    }
    for (int ii = 2; ii <= n; ++ii) {
        int i = ii - 1, k = i;
        float p = d[i];
        for (int j = ii; j <= n; ++j) if (d[j] < p) { k = j; p = d[j]; }
        if (k != i) {
            d[k] = d[i]; d[i] = p;
            for (int r2 = 0; r2 < 3; ++r2) {
                float t = z[r2][i - 1]; z[r2][i - 1] = z[r2][k - 1]; z[r2][k - 1] = t;
            }
        }
    }
}

__device__ void eigh3(const float A[6], float V[3][3]) {
    float a00 = A[0], a10 = A[1], a20 = A[2], a11 = A[3], a21 = A[4], a22 = A[5];
    float tau = 0.f, v2 = 0.f, e0, e1, d1 = a11, d2v = a22;
    float xnorm = fabsf(a20);
    if (xnorm == 0.f) { tau = 0.f; e0 = a10; e1 = a21; }
    else {
        float alpha = a10;
        float beta = -copysignf(slapy2f(alpha, xnorm), alpha);
        tau = (beta - alpha) / beta;
        v2 = a20 * (1.f / (alpha - beta));
        e0 = beta;
        float w0 = tau * a11 + tau * (a21 * v2);
        float w1 = tau * a21 + (tau * v2) * a22;
        float aw = -0.5f * tau * (w0 + w1 * v2);
        w0 += aw; w1 += aw * v2;
        d1  = (a11 - w0) - w0;
        e1  = (a21 - v2 * w0) - w1;
        d2v = (a22 - v2 * w1) - w1 * v2;
    }
    float d[3] = {a00, d1, d2v};
    float e[2] = {e0, e1};
    ssteqr3(d, e, V);
    if (tau != 0.f) {
        for (int j = 0; j < 3; ++j) {
            float s = V[1][j] + v2 * V[2][j];
            V[1][j] -= tau * s;
            V[2][j] -= tau * v2 * s;
        }
    }
}

// ---------------------------------------------------------------------------
__device__ __forceinline__ unsigned long long warp_min64(unsigned long long k) {
    unsigned hi = (unsigned)(k >> 32), lo = (unsigned)k;
    unsigned mhi = __reduce_min_sync(0xffffffffu, hi);
    unsigned lo2 = (hi == mhi) ? lo : 0xffffffffu;
    unsigned mlo = __reduce_min_sync(0xffffffffu, lo2);
    return ((unsigned long long)mhi << 32) | mlo;
}

__device__ __forceinline__ unsigned f2u(float f) {
    int i = __float_as_int(f);
    return (i < 0) ? ~(unsigned)i : ((unsigned)i | 0x80000000u);
}

// prep + coef transpose fused into one launch
__global__ void setup_kernel(const float* __restrict__ pos,
                             const float* __restrict__ coef) {
    int i = blockIdx.x * blockDim.x + threadIdx.x;
    if (i < NP) {
        float x = pos[3 * i], y = pos[3 * i + 1], z = pos[3 * i + 2];
        g_posq[i] = make_float4(x, y, z, x * x + y * y + z * z);
    }
    if (i < COUT * NG) {
        int o = i / NG, j = i - o * NG;
        g_coefT[(j >> 2) * 128 + o * 4 + (j & 3)] = coef[i];
    }
}

// ---------------------------------------------------------------------------
// Kernel 1: exact kNN, 8 queries per block.
// Extraction: per-lane register-sorted survivor lists (no LDS in the round
// chain); exact same winners in same order (unique keys, ascending).
// ---------------------------------------------------------------------------
__global__ __launch_bounds__(256)
void knn_kernel() {
    const int tid = threadIdx.x;
    const int lane = tid & 31;
    const int wid = tid >> 5;
    const int qbase = blockIdx.x * QB;

    __shared__ unsigned long long s_surv[QB][SCAP];
    __shared__ unsigned s_b4[QB][8];
    __shared__ int s_cnt[QB];

    if (tid < QB) s_cnt[tid] = 0;

    float4 pq[QB];
#pragma unroll
    for (int q = 0; q < QB; ++q) pq[q] = g_posq[qbase + q];

    // ---- Pass 1: per-thread min d2 per query over its 16 candidates --------
    float mn[QB];
#pragma unroll
    for (int q = 0; q < QB; ++q) mn[q] = __int_as_float(0x7f800000);

#pragma unroll 4
    for (int j = 0; j < 16; ++j) {
        int cand = tid + (j << 8);
        float4 cq = g_posq[cand];
#pragma unroll
        for (int q = 0; q < QB; ++q) {
            float dot = pq[q].x * cq.x + pq[q].y * cq.y + pq[q].z * cq.z;
            float d2 = (pq[q].w + cq.w) - 2.f * dot;
            mn[q] = fminf(mn[q], d2);
        }
    }

    // ---- Bound per query: max over warps of warp-4th-smallest thread-min ---
#pragma unroll
    for (int q = 0; q < QB; ++q) {
        unsigned h = f2u(mn[q]), w4 = 0;
#pragma unroll
        for (int r = 0; r < 4; ++r) {
            w4 = __reduce_min_sync(0xffffffffu, h);
            if (h == w4) h = 0xffffffffu;
        }
        if (lane == 0) s_b4[q][wid] = w4;
    }
    __syncthreads();

    float Bf[QB];
#pragma unroll
    for (int q = 0; q < QB; ++q) {
        unsigned B = s_b4[q][0];
#pragma unroll
        for (int w = 1; w < 8; ++w) B = max(B, s_b4[q][w]);
        int bi = (B & 0x80000000u) ? (int)(B & 0x7fffffffu) : (int)~B;
        Bf[q] = __int_as_float(bi);
    }

    // ---- Pass 2: q-outer with early-out ------------------------------------
#pragma unroll
    for (int q = 0; q < QB; ++q) {
        if (mn[q] <= Bf[q]) {
#pragma unroll 4
            for (int j = 0; j < 16; ++j) {
                int cand = tid + (j << 8);
                float4 cq = g_posq[cand];
                float dot = pq[q].x * cq.x + pq[q].y * cq.y + pq[q].z * cq.z;
                float d2 = (pq[q].w + cq.w) - 2.f * dot;
                if (d2 <= Bf[q]) {
                    unsigned u = f2u(d2);
                    int pos = atomicAdd(&s_cnt[q], 1);
                    if (pos < SCAP)
                        s_surv[q][pos] = ((unsigned long long)u << 32) | (unsigned)cand;
                }
            }
        }
    }
    __syncthreads();

    // ---- Extraction: warp w extracts top-32 of query w ----------------------
    {
        const int q = wid;
        int S = s_cnt[q] < SCAP ? s_cnt[q] : SCAP;
        if (S <= 256) {
            // register-resident path: <=8 survivors per lane, sorted ascending
            unsigned long long k0, k1, k2, k3, k4, k5, k6, k7;
            k0 = (lane        < S) ? s_surv[q][lane]        : ~0ULL;
            k1 = (lane +  32  < S) ? s_surv[q][lane +  32]  : ~0ULL;
            k2 = (lane +  64  < S) ? s_surv[q][lane +  64]  : ~0ULL;
            k3 = (lane +  96  < S) ? s_surv[q][lane +  96]  : ~0ULL;
            k4 = (lane + 128  < S) ? s_surv[q][lane + 128]  : ~0ULL;
            k5 = (lane + 160  < S) ? s_surv[q][lane + 160]  : ~0ULL;
            k6 = (lane + 192  < S) ? s_surv[q][lane + 192]  : ~0ULL;
            k7 = (lane + 224  < S) ? s_surv[q][lane + 224]  : ~0ULL;
            // Batcher odd-even mergesort for 8 (19 compare-exchanges)
#define CE(a, b) { if (a > b) { unsigned long long t = a; a = b; b = t; } }
            CE(k0, k1) CE(k2, k3) CE(k4, k5) CE(k6, k7)
            CE(k0, k2) CE(k1, k3) CE(k1, k2)
            CE(k4, k6) CE(k5, k7) CE(k5, k6)
            CE(k0, k4) CE(k1, k5) CE(k2, k6) CE(k3, k7)
            CE(k2, k4) CE(k3, k5)
            CE(k1, k2) CE(k3, k4) CE(k5, k6)
#undef CE
#pragma unroll
            for (int r = 0; r < KNN; ++r) {
                unsigned long long w = warp_min64(k0);
                if (lane == 0) g_nbr[(qbase + q) * KNN + r] = (int)(w & 0xffffffffu);
                if (k0 == w) {              // unique key -> exactly one popper
                    k0 = k1; k1 = k2; k2 = k3; k3 = k4;
                    k4 = k5; k5 = k6; k6 = k7; k7 = ~0ULL;
                }
            }
        } else {
            // fallback (rare): original smem-scan loop
            for (int r = 0; r < KNN; ++r) {
                unsigned long long m = ~0ULL; int mi = -1;
                for (int i = lane; i < S; i += 32) {
                    unsigned long long v = s_surv[q][i];
                    if (v < m) { m = v; mi = i; }
                }
                unsigned long long w = warp_min64(m);
                if (m == w && mi >= 0) s_surv[q][mi] = ~0ULL;
                if (lane == 0) g_nbr[(qbase + q) * KNN + r] = (int)(w & 0xffffffffu);
            }
        }
    }
}

// ---------------------------------------------------------------------------
// Kernel 2: frames — one warp per point (validated R10, ~15us)
// ---------------------------------------------------------------------------
__global__ __launch_bounds__(128)
void frame_kernel(float* __restrict__ centers_out) {
    const int tid = threadIdx.x;
    const int lane = tid & 31;
    const int wid = tid >> 5;
    const int p = blockIdx.x * 4 + wid;

    const int nb = g_nbr[p * KNN + lane];
    const float4 q = g_posq[nb];

    float cx = q.x, cy = q.y, cz = q.z;
#pragma unroll
    for (int off = 16; off; off >>= 1) {
        cx += __shfl_xor_sync(0xffffffffu, cx, off);
        cy += __shfl_xor_sync(0xffffffffu, cy, off);
        cz += __shfl_xor_sync(0xffffffffu, cz, off);
    }
    cx *= 0.03125f; cy *= 0.03125f; cz *= 0.03125f;
    if (lane == 0) {
        centers_out[3 * p]     = cx;
        centers_out[3 * p + 1] = cy;
        centers_out[3 * p + 2] = cz;
    }

    const float lx = q.x - cx, ly = q.y - cy, lz = q.z - cz;
    float c00 = lx * lx, c01 = lx * ly, c02 = lx * lz;
    float c11 = ly * ly, c12 = ly * lz, c22 = lz * lz;
#pragma unroll
    for (int off = 16; off; off >>= 1) {
        c00 += __shfl_xor_sync(0xffffffffu, c00, off);
        c01 += __shfl_xor_sync(0xffffffffu, c01, off);
        c02 += __shfl_xor_sync(0xffffffffu, c02, off);
        c11 += __shfl_xor_sync(0xffffffffu, c11, off);
        c12 += __shfl_xor_sync(0xffffffffu, c12, off);
        c22 += __shfl_xor_sync(0xffffffffu, c22, off);
    }
    if (lane == 0) {
        float A[6] = {c00 * 0.03125f, c01 * 0.03125f, c02 * 0.03125f,
                      c11 * 0.03125f, c12 * 0.03125f, c22 * 0.03125f};
        float V[3][3];
        eigh3(A, V);
        g_frame[p * 3 + 0] = make_float4(cx, cy, cz, V[0][0]);
        g_frame[p * 3 + 1] = make_float4(V[0][1], V[0][2], V[1][0], V[1][1]);
        g_frame[p * 3 + 2] = make_float4(V[1][2], V[2][0], V[2][1], V[2][2]);
    }
}

// ---------------------------------------------------------------------------
// Kernel 3: conv — one warp per point (R10 structure, 28.9us) + occupancy cap
// ---------------------------------------------------------------------------
__global__ __launch_bounds__(128, 8)
void conv_kernel(const float* __restrict__ chan,
                 float* __restrict__ out) {
    const int tid = threadIdx.x;
    const int lane = tid & 31;
    const int wid = tid >> 5;
    const int p = blockIdx.x * 4 + wid;

    __shared__ float s_basis[4][32][28];
    __shared__ float s_G[4][448];
    __shared__ float s_feat[4][32][16];

    const int nb = g_nbr[p * KNN + lane];
    const float4 q = g_posq[nb];

    // preload this lane's neighbor features (coalesced float4)
    {
        const float4* fr = (const float4*)(chan + nb * CIN);
        float4 f0 = fr[0], f1 = fr[1], f2 = fr[2], f3 = fr[3];
        float4* sf = (float4*)&s_feat[wid][lane][0];
        sf[0] = f0; sf[1] = f1; sf[2] = f2; sf[3] = f3;
    }

    // frame (broadcast loads — all lanes same address)
    const float4 f0 = __ldg(&g_frame[p * 3 + 0]);
    const float4 f1 = __ldg(&g_frame[p * 3 + 1]);
    const float4 f2 = __ldg(&g_frame[p * 3 + 2]);
    const float cx = f0.x, cy = f0.y, cz = f0.z;
    const float v00 = f0.w, v01 = f1.x, v02 = f1.y;
    const float v10 = f1.z, v11 = f1.w, v12 = f2.x;
    const float v20 = f2.y, v21 = f2.z, v22 = f2.w;

    const float lx = q.x - cx, ly = q.y - cy, lz = q.z - cz;

    // rotate into PCA frame, spherical coords, 27 basis values
    {
        float x = lx * v00 + ly * v10 + lz * v20;
        float y = lx * v01 + ly * v11 + lz * v21;
        float z = lx * v02 + ly * v12 + lz * v22;
        float r = sqrtf(x * x + y * y + z * z);
        float ct = z / (r + 1e-8f);
        ct = fminf(fmaxf(ct, -1.f + 1e-6f), 1.f - 1e-6f);
        float theta = acosf(ct);
        float phi = atan2f(y, x);
        float rb[3] = {1.f, r, r * r};
        float tb[3] = {1.f, cosf(theta), cosf(2.f * theta)};
        float pb[3] = {1.f, cosf(phi), cosf(2.f * phi)};
#pragma unroll
        for (int n = 0; n < 3; ++n)
#pragma unroll
            for (int l = 0; l < 3; ++l)
#pragma unroll
                for (int m = 0; m < 3; ++m)
                    s_basis[wid][lane][n * 9 + l * 3 + m] = (rb[n] * tb[l]) * pb[m];
        s_basis[wid][lane][27] = 0.f;    // pad for half=1 float4 path
    }
    __syncwarp();

    // phase 4: G[c*27+nlm] = sum_k basis[k][nlm]*feat[k][c]
    {
        const int c = lane >> 1;
        const int half = lane & 1;
        float acc[16];
#pragma unroll
        for (int i = 0; i < 16; ++i) acc[i] = 0.f;

#pragma unroll 8
        for (int k = 0; k < KNN; ++k) {
            float fv = s_feat[wid][k][c];
            const float* row = &s_basis[wid][k][0];
            if (half == 0) {
                float4 b0 = *(const float4*)(row);
                float4 b1 = *(const float4*)(row + 4);
                float4 b2 = *(const float4*)(row + 8);
                float4 b3 = *(const float4*)(row + 12);
                acc[0]  += b0.x * fv; acc[1]  += b0.y * fv; acc[2]  += b0.z * fv; acc[3]  += b0.w * fv;
                acc[4]  += b1.x * fv; acc[5]  += b1.y * fv; acc[6]  += b1.z * fv; acc[7]  += b1.w * fv;
                acc[8]  += b2.x * fv; acc[9]  += b2.y * fv; acc[10] += b2.z * fv; acc[11] += b2.w * fv;
                acc[12] += b3.x * fv; acc[13] += b3.y * fv; acc[14] += b3.z * fv; acc[15] += b3.w * fv;
            } else {
                float4 b0 = *(const float4*)(row + 16);
                float4 b1 = *(const float4*)(row + 20);
                float4 b2 = *(const float4*)(row + 24);
                acc[0]  += b0.x * fv; acc[1]  += b0.y * fv; acc[2]  += b0.z * fv; acc[3]  += b0.w * fv;
                acc[4]  += b1.x * fv; acc[5]  += b1.y * fv; acc[6]  += b1.z * fv; acc[7]  += b1.w * fv;
                acc[8]  += b2.x * fv; acc[9]  += b2.y * fv; acc[10] += b2.z * fv;
            }
        }
        if (half == 0) {
#pragma unroll
            for (int i = 0; i < 16; ++i) s_G[wid][c * 27 + i] = acc[i];
        } else {
#pragma unroll
            for (int i = 0; i < 11; ++i) s_G[wid][c * 27 + 16 + i] = acc[i];
        }
    }
    __syncwarp();

    // phase 5: out[o=lane] = sum_j coefT[j][o] * G[j]
    {
        float a0 = 0.f, a1 = 0.f, a2 = 0.f, a3 = 0.f;
        const float* gT = g_coefT + lane * 4;
        const float* gw = &s_G[wid][0];
#pragma unroll 8
        for (int t = 0; t < 108; ++t) {
            float4 cf = *(const float4*)(gT + t * 128);
            float4 gv = *(const float4*)(gw + t * 4);
            a0 += cf.x * gv.x;
            a1 += cf.y * gv.y;
            a2 += cf.z * gv.z;
            a3 += cf.w * gv.w;
        }
        out[p * COUT + lane] = (a0 + a1) + (a2 + a3);
    }
}

extern "C" void kernel_launch(void* const* d_in, const int* in_sizes, int n_in,
                              void* d_out, int out_size) {
    const float* pos  = (const float*)d_in[0];
    const float* chan = (const float*)d_in[1];
    const float* coef = (const float*)d_in[3];

    float* d_outf = (float*)d_out;
    float* centers_ptr;
    float* out_ptr;
    if (out_size == NP * 3 + NP * COUT) {
        centers_ptr = d_outf;
        out_ptr     = d_outf + NP * 3;
    } else if (out_size == NP * COUT) {
        cudaGetSymbolAddress((void**)&centers_ptr, g_cscratch);
        out_ptr = d_outf;
    } else {
        centers_ptr = d_outf;
        cudaGetSymbolAddress((void**)&out_ptr, g_oscratch);
    }

    setup_kernel<<<54, 256>>>(pos, coef);
    knn_kernel<<<NP / QB, 256>>>();
    frame_kernel<<<NP / 4, 128>>>(centers_ptr);
    conv_kernel<<<NP / 4, 128>>>(chan, out_ptr);
}

// round 14
// speedup vs baseline: 1.1382x; 1.0016x over previous
#include <cuda_runtime.h>
#include <cuda_bf16.h>

#define NP   4096
#define KNN  32
#define CIN  16
#define COUT 32
#define NB   27
#define NG   432
#define QB   8        // queries per knn block
#define SCAP 384      // survivor cap per query

__device__ float4 g_posq[NP];
__device__ int    g_nbr[NP * KNN];
__device__ float  g_coefT[108 * 128];     // [j/4][o][j%4]
__device__ float4 g_frame[NP * 3];        // (cx,cy,cz,V00),(V01,V02,V10,V11),(V12,V20,V21,V22)
__device__ float  g_cscratch[NP * 3];
__device__ float  g_oscratch[NP * COUT];

// ---------------------------------------------------------------------------
// LAPACK fp32 helpers (LAPACK >= 3.10 conventions) — validated R2..R12.
// ssteqr3_reg: identical operation sequence to the validated array version,
// but all runtime-indexed locals flattened to registers (no LDL/STL).
// ---------------------------------------------------------------------------
__device__ __forceinline__ float slapy2f(float x, float y) {
    float xa = fabsf(x), ya = fabsf(y);
    float w = fmaxf(xa, ya), z = fminf(xa, ya);
    if (z == 0.f) return w;
    float t = z / w;
    return w * sqrtf(1.f + t * t);
}

__device__ __forceinline__ void slartgf(float f, float g, float* c, float* s, float* r) {
    if (g == 0.f)      { *c = 1.f; *s = 0.f; *r = f; }
    else if (f == 0.f) { *c = 0.f; *s = (g > 0.f) ? 1.f : -1.f; *r = fabsf(g); }
    else {
        float d = sqrtf(f * f + g * g);
        float p = 1.f / d;
        *c = fabsf(f) * p;
        *s = g * copysignf(p, f);
        *r = copysignf(d, f);
    }
}

__device__ void slaev2f(float a, float b, float c, float* rt1, float* rt2,
                        float* cs1, float* sn1) {
    float sm = a + c, df = a - c;
    float adf = fabsf(df);
    float tb = b + b, ab = fabsf(tb);
    float acmx, acmn;
    if (fabsf(a) > fabsf(c)) { acmx = a; acmn = c; } else { acmx = c; acmn = a; }
    float rt;
    if (adf > ab)      { float t = ab / adf; rt = adf * sqrtf(1.f + t * t); }
    else if (adf < ab) { float t = adf / ab; rt = ab * sqrtf(1.f + t * t); }
    else               rt = ab * sqrtf(2.f);
    int sgn1;
    if (sm < 0.f)      { *rt1 = 0.5f * (sm - rt); sgn1 = -1;
                         *rt2 = (acmx / *rt1) * acmn - (b / *rt1) * b; }
    else if (sm > 0.f) { *rt1 = 0.5f * (sm + rt); sgn1 = 1;
                         *rt2 = (acmx / *rt1) * acmn - (b / *rt1) * b; }
    else               { *rt1 = 0.5f * rt; *rt2 = -0.5f * rt; sgn1 = 1; }
    float cs; int sgn2;
    if (df >= 0.f) { cs = df + rt; sgn2 = 1; } else { cs = df - rt; sgn2 = -1; }
    float acs = fabsf(cs);
    if (acs > ab) {
        float ct = -tb / cs;
        *sn1 = 1.f / sqrtf(1.f + ct * ct);
        *cs1 = ct * *sn1;
    } else {
        if (ab == 0.f) { *cs1 = 1.f; *sn1 = 0.f; }
        else {
            float tn = -cs / tb;
            *cs1 = 1.f / sqrtf(1.f + tn * tn);
            *sn1 = tn * *cs1;
        }
    }
    if (sgn1 == sgn2) { float tn = *cs1; *cs1 = -*sn1; *sn1 = tn; }
}

// Register-resident ssteqr('I', n=3). Indices: d in {1,2,3}; e/wc/ws in {1,2};
// z rotations touch adjacent column pairs only (hi in {1,2}).
__device__ void ssteqr3_reg(float D1, float D2, float D3, float E1, float E2,
                            float V[3][3]) {
    const float eps = 5.9604645e-08f, eps2 = eps * eps, safmin = 1.17549435e-38f;
    const int n = 3, nmaxit = 90;
    float d1_ = D1, d2_ = D2, d3_ = D3;
    float e1_ = E1, e2_ = E2;
    float z00 = 1.f, z01 = 0.f, z02 = 0.f;
    float z10 = 0.f, z11 = 1.f, z12 = 0.f;
    float z20 = 0.f, z21 = 0.f, z22 = 1.f;
    float wc1_ = 0.f, wc2_ = 0.f, ws1_ = 0.f, ws2_ = 0.f;

    auto GETD = [&](int i) -> float { return i == 1 ? d1_ : (i == 2 ? d2_ : d3_); };
    auto SETD = [&](int i, float v) { if (i == 1) d1_ = v; else if (i == 2) d2_ = v; else d3_ = v; };
    auto GETE = [&](int i) -> float { return i == 1 ? e1_ : e2_; };
    auto SETE = [&](int i, float v) { if (i == 1) e1_ = v; else e2_ = v; };
    auto GETWC = [&](int i) -> float { return i == 1 ? wc1_ : wc2_; };
    auto SETWC = [&](int i, float v) { if (i == 1) wc1_ = v; else wc2_ = v; };
    auto GETWS = [&](int i) -> float { return i == 1 ? ws1_ : ws2_; };
    auto SETWS = [&](int i, float v) { if (i == 1) ws1_ = v; else ws2_ = v; };
    // rotate columns (hi, hi-1), 0-based hi in {1,2}:
    // t=z[i][hi]; z[i][hi]=cc*t-ss*z[i][hi-1]; z[i][hi-1]=ss*t+cc*z[i][hi-1]
    auto ZROT = [&](int hi, float cc, float ss) {
        if (hi == 1) {
            float t;
            t = z01; z01 = cc * t - ss * z00; z00 = ss * t + cc * z00;
            t = z11; z11 = cc * t - ss * z10; z10 = ss * t + cc * z10;
            t = z21; z21 = cc * t - ss * z20; z20 = ss * t + cc * z20;
        } else {
            float t;
            t = z02; z02 = cc * t - ss * z01; z01 = ss * t + cc * z01;
            t = z12; z12 = cc * t - ss * z11; z11 = ss * t + cc * z11;
            t = z22; z22 = cc * t - ss * z21; z21 = ss * t + cc * z21;
        }
    };
    auto ZSWAP = [&](int a, int b) {   // swap columns a<b
        float t;
        if (a == 0 && b == 1) {
            t = z00; z00 = z01; z01 = t;
            t = z10; z10 = z11; z11 = t;
            t = z20; z20 = z21; z21 = t;
        } else if (a == 0) {           // (0,2)
            t = z00; z00 = z02; z02 = t;
            t = z10; z10 = z12; z12 = t;
            t = z20; z20 = z22; z22 = t;
        } else {                       // (1,2)
            t = z01; z01 = z02; z02 = t;
            t = z11; z11 = z12; z12 = t;
            t = z21; z21 = z22; z22 = t;
        }
    };

    int jtot = 0, l1 = 1;

    while (l1 <= n) {
        if (l1 > 1) SETE(l1 - 1, 0.f);
        int m = n;
        for (int mm = l1; mm <= n - 1; ++mm) {
            float tst = fabsf(GETE(mm));
            if (tst == 0.f) { m = mm; break; }
            if (tst <= (sqrtf(fabsf(GETD(mm))) * sqrtf(fabsf(GETD(mm + 1)))) * eps) {
                SETE(mm, 0.f); m = mm; break;
            }
        }
        int l = l1;
        int lsv = l, lend = m, lendsv = lend;
        l1 = m + 1;
        if (lend == l) continue;
        if (fabsf(GETD(lend)) < fabsf(GETD(l))) { lend = lsv; l = lendsv; }

        if (lend > l) {
            // ---- QL ----
            for (;;) {
                int mq = lend;
                if (l != lend) {
                    for (int mi = l; mi <= lend - 1; ++mi) {
                        float tst = GETE(mi) * GETE(mi);
                        if (tst <= (eps2 * fabsf(GETD(mi))) * fabsf(GETD(mi + 1)) + safmin) {
                            mq = mi; break;
                        }
                    }
                }
                if (mq < lend) SETE(mq, 0.f);
                float p = GETD(l);
                if (mq == l) { SETD(l, p); if (++l <= lend) continue; break; }
                if (mq == l + 1) {
                    float rt1, rt2, c, s;
                    slaev2f(GETD(l), GETE(l), GETD(l + 1), &rt1, &rt2, &c, &s);
                    ZROT(l, c, s);
                    SETD(l, rt1); SETD(l + 1, rt2); SETE(l, 0.f);
                    l += 2;
                    if (l <= lend) continue;
                    break;
                }
                if (jtot == nmaxit) break;
                ++jtot;
                float g = (GETD(l + 1) - p) / (2.f * GETE(l));
                float r = slapy2f(g, 1.f);
                g = GETD(mq) - p + (GETE(l) / (g + copysignf(r, g)));
                float s = 1.f, c = 1.f; p = 0.f;
                for (int i = mq - 1; i >= l; --i) {
                    float f = s * GETE(i), b = c * GETE(i);
                    slartgf(g, f, &c, &s, &r);
                    if (i != mq - 1) SETE(i + 1, r);
                    g = GETD(i + 1) - p;
                    r = (GETD(i) - g) * s + 2.f * c * b;
                    p = s * r;
                    SETD(i + 1, g + p);
                    g = c * r - b;
                    SETWC(i, c); SETWS(i, -s);
                }
                for (int j = mq - l; j >= 1; --j) {
                    int hi = l + j - 1;
                    ZROT(hi, GETWC(hi), GETWS(hi));
                }
                SETD(l, GETD(l) - p);
                SETE(l, g);
            }
        } else {
            // ---- QR ----
            for (;;) {
                int mq = lend;
                if (l != lend) {
                    for (int mi = l; mi >= lend + 1; --mi) {
                        float tst = GETE(mi - 1) * GETE(mi - 1);
                        if (tst <= (eps2 * fabsf(GETD(mi))) * fabsf(GETD(mi - 1)) + safmin) {
                            mq = mi; break;
                        }
                    }
                }
                if (mq > lend) SETE(mq - 1, 0.f);
                float p = GETD(l);
                if (mq == l) { SETD(l, p); if (--l >= lend) continue; break; }
                if (mq == l - 1) {
                    float rt1, rt2, c, s;
                    slaev2f(GETD(l - 1), GETE(l - 1), GETD(l), &rt1, &rt2, &c, &s);
                    ZROT(l - 1, c, s);
                    SETD(l - 1, rt1); SETD(l, rt2); SETE(l - 1, 0.f);
                    l -= 2;
                    if (l >= lend) continue;
                    break;
                }
                if (jtot == nmaxit) break;
                ++jtot;
                float g = (GETD(l - 1) - p) / (2.f * GETE(l - 1));
                float r = slapy2f(g, 1.f);
                g = GETD(mq) - p + (GETE(l - 1) / (g + copysignf(r, g)));
                float s = 1.f, c = 1.f; p = 0.f;
                for (int i = mq; i <= l - 1; ++i) {
                    float f = s * GETE(i), b = c * GETE(i);
                    slartgf(g, f, &c, &s, &r);
                    if (i != mq) SETE(i - 1, r);
                    g = GETD(i) - p;
                    r = (GETD(i + 1) - g) * s + 2.f * c * b;
                    p = s * r;
                    SETD(i, g + p);
                    g = c * r - b;
                    SETWC(i, c); SETWS(i, s);
                }
                for (int j = 1; j <= l - mq; ++j) {
                    int hi = mq + j - 1;
                    ZROT(hi, GETWC(hi), GETWS(hi));
                }
                SETD(l, GETD(l) - p);
                SETE(l - 1, g);
            }
        }
    }
    // selection sort ascending, swap eigvec columns
    for (int ii = 2; ii <= n; ++ii) {
        int i = ii - 1, k = i;
        float p = GETD(i);
        for (int j = ii; j <= n; ++j) if (GETD(j) < p) { k = j; p = GETD(j); }
        if (k != i) {
            SETD(k, GETD(i)); SETD(i, p);
            ZSWAP(i - 1, k - 1);
        }
    }

    V[0][0] = z00; V[0][1] = z01; V[0][2] = z02;
    V[1][0] = z10; V[1][1] = z11; V[1][2] = z12;
    V[2][0] = z20; V[2][1] = z21; V[2][2] = z22;
}

__device__ void eigh3(const float A[6], float V[3][3]) {
    float a00 = A[0], a10 = A[1], a20 = A[2], a11 = A[3], a21 = A[4], a22 = A[5];
    float tau = 0.f, v2 = 0.f, e0, e1, d1 = a11, d2v = a22;
    float xnorm = fabsf(a20);
    if (xnorm == 0.f) { tau = 0.f; e0 = a10; e1 = a21; }
    else {
        float alpha = a10;
        float beta = -copysignf(slapy2f(alpha, xnorm), alpha);
        tau = (beta - alpha) / beta;
        v2 = a20 * (1.f / (alpha - beta));
        e0 = beta;
        float w0 = tau * a11 + tau * (a21 * v2);
        float w1 = tau * a21 + (tau * v2) * a22;
        float aw = -0.5f * tau * (w0 + w1 * v2);
        w0 += aw; w1 += aw * v2;
        d1  = (a11 - w0) - w0;
        e1  = (a21 - v2 * w0) - w1;
        d2v = (a22 - v2 * w1) - w1 * v2;
    }
    ssteqr3_reg(a00, d1, d2v, e0, e1, V);
    if (tau != 0.f) {
        for (int j = 0; j < 3; ++j) {
            float s = V[1][j] + v2 * V[2][j];
            V[1][j] -= tau * s;
            V[2][j] -= tau * v2 * s;
        }
    }
}

// ---------------------------------------------------------------------------
__device__ __forceinline__ unsigned long long warp_min64(unsigned long long k) {
    unsigned hi = (unsigned)(k >> 32), lo = (unsigned)k;
    unsigned mhi = __reduce_min_sync(0xffffffffu, hi);
    unsigned lo2 = (hi == mhi) ? lo : 0xffffffffu;
    unsigned mlo = __reduce_min_sync(0xffffffffu, lo2);
    return ((unsigned long long)mhi << 32) | mlo;
}

__device__ __forceinline__ unsigned f2u(float f) {
    int i = __float_as_int(f);
    return (i < 0) ? ~(unsigned)i : ((unsigned)i | 0x80000000u);
}

// prep + coef transpose (destination-major -> fully coalesced writes)
__global__ void setup_kernel(const float* __restrict__ pos,
                             const float* __restrict__ coef) {
    int i = blockIdx.x * blockDim.x + threadIdx.x;
    if (i < NP) {
        float x = pos[3 * i], y = pos[3 * i + 1], z = pos[3 * i + 2];
        g_posq[i] = make_float4(x, y, z, x * x + y * y + z * z);
    }
    if (i < COUT * NG) {
        int t = i >> 7;              // dest tile [t][o][m], 128 per tile
        int rem = i & 127;
        int o = rem >> 2, m2 = rem & 3;
        g_coefT[i] = coef[o * NG + t * 4 + m2];
    }
}

// ---------------------------------------------------------------------------
// Kernel 1: exact kNN, 8 queries per block (R12 version, register extraction)
// ---------------------------------------------------------------------------
__global__ __launch_bounds__(256)
void knn_kernel() {
    const int tid = threadIdx.x;
    const int lane = tid & 31;
    const int wid = tid >> 5;
    const int qbase = blockIdx.x * QB;

    __shared__ unsigned long long s_surv[QB][SCAP];
    __shared__ unsigned s_b4[QB][8];
    __shared__ int s_cnt[QB];

    if (tid < QB) s_cnt[tid] = 0;

    float4 pq[QB];
#pragma unroll
    for (int q = 0; q < QB; ++q) pq[q] = g_posq[qbase + q];

    float mn[QB];
#pragma unroll
    for (int q = 0; q < QB; ++q) mn[q] = __int_as_float(0x7f800000);

#pragma unroll 4
    for (int j = 0; j < 16; ++j) {
        int cand = tid + (j << 8);
        float4 cq = g_posq[cand];
#pragma unroll
        for (int q = 0; q < QB; ++q) {
            float dot = pq[q].x * cq.x + pq[q].y * cq.y + pq[q].z * cq.z;
            float d2 = (pq[q].w + cq.w) - 2.f * dot;
            mn[q] = fminf(mn[q], d2);
        }
    }

#pragma unroll
    for (int q = 0; q < QB; ++q) {
        unsigned h = f2u(mn[q]), w4 = 0;
#pragma unroll
        for (int r = 0; r < 4; ++r) {
            w4 = __reduce_min_sync(0xffffffffu, h);
            if (h == w4) h = 0xffffffffu;
        }
        if (lane == 0) s_b4[q][wid] = w4;
    }
    __syncthreads();

    float Bf[QB];
#pragma unroll
    for (int q = 0; q < QB; ++q) {
        unsigned B = s_b4[q][0];
#pragma unroll
        for (int w = 1; w < 8; ++w) B = max(B, s_b4[q][w]);
        int bi = (B & 0x80000000u) ? (int)(B & 0x7fffffffu) : (int)~B;
        Bf[q] = __int_as_float(bi);
    }

#pragma unroll
    for (int q = 0; q < QB; ++q) {
        if (mn[q] <= Bf[q]) {
#pragma unroll 4
            for (int j = 0; j < 16; ++j) {
                int cand = tid + (j << 8);
                float4 cq = g_posq[cand];
                float dot = pq[q].x * cq.x + pq[q].y * cq.y + pq[q].z * cq.z;
                float d2 = (pq[q].w + cq.w) - 2.f * dot;
                if (d2 <= Bf[q]) {
                    unsigned u = f2u(d2);
                    int pos = atomicAdd(&s_cnt[q], 1);
                    if (pos < SCAP)
                        s_surv[q][pos] = ((unsigned long long)u << 32) | (unsigned)cand;
                }
            }
        }
    }
    __syncthreads();

    {
        const int q = wid;
        int S = s_cnt[q] < SCAP ? s_cnt[q] : SCAP;
        if (S <= 256) {
            unsigned long long k0, k1, k2, k3, k4, k5, k6, k7;
            k0 = (lane        < S) ? s_surv[q][lane]        : ~0ULL;
            k1 = (lane +  32  < S) ? s_surv[q][lane +  32]  : ~0ULL;
            k2 = (lane +  64  < S) ? s_surv[q][lane +  64]  : ~0ULL;
            k3 = (lane +  96  < S) ? s_surv[q][lane +  96]  : ~0ULL;
            k4 = (lane + 128  < S) ? s_surv[q][lane + 128]  : ~0ULL;
            k5 = (lane + 160  < S) ? s_surv[q][lane + 160]  : ~0ULL;
            k6 = (lane + 192  < S) ? s_surv[q][lane + 192]  : ~0ULL;
            k7 = (lane + 224  < S) ? s_surv[q][lane + 224]  : ~0ULL;
#define CE(a, b) { if (a > b) { unsigned long long t = a; a = b; b = t; } }
            CE(k0, k1) CE(k2, k3) CE(k4, k5) CE(k6, k7)
            CE(k0, k2) CE(k1, k3) CE(k1, k2)
            CE(k4, k6) CE(k5, k7) CE(k5, k6)
            CE(k0, k4) CE(k1, k5) CE(k2, k6) CE(k3, k7)
            CE(k2, k4) CE(k3, k5)
            CE(k1, k2) CE(k3, k4) CE(k5, k6)
#undef CE
#pragma unroll
            for (int r = 0; r < KNN; ++r) {
                unsigned long long w = warp_min64(k0);
                if (lane == 0) g_nbr[(qbase + q) * KNN + r] = (int)(w & 0xffffffffu);
                if (k0 == w) {
                    k0 = k1; k1 = k2; k2 = k3; k3 = k4;
                    k4 = k5; k5 = k6; k6 = k7; k7 = ~0ULL;
                }
            }
        } else {
            for (int r = 0; r < KNN; ++r) {
                unsigned long long m = ~0ULL; int mi = -1;
                for (int i = lane; i < S; i += 32) {
                    unsigned long long v = s_surv[q][i];
                    if (v < m) { m = v; mi = i; }
                }
                unsigned long long w = warp_min64(m);
                if (m == w && mi >= 0) s_surv[q][mi] = ~0ULL;
                if (lane == 0) g_nbr[(qbase + q) * KNN + r] = (int)(w & 0xffffffffu);
            }
        }
    }
}

// ---------------------------------------------------------------------------
// Kernel 2: frames — one warp per point; eigh now fully register-resident
// ---------------------------------------------------------------------------
__global__ __launch_bounds__(128)
void frame_kernel(float* __restrict__ centers_out) {
    const int tid = threadIdx.x;
    const int lane = tid & 31;
    const int wid = tid >> 5;
    const int p = blockIdx.x * 4 + wid;

    const int nb = g_nbr[p * KNN + lane];
    const float4 q = g_posq[nb];

    float cx = q.x, cy = q.y, cz = q.z;
#pragma unroll
    for (int off = 16; off; off >>= 1) {
        cx += __shfl_xor_sync(0xffffffffu, cx, off);
        cy += __shfl_xor_sync(0xffffffffu, cy, off);
        cz += __shfl_xor_sync(0xffffffffu, cz, off);
    }
    cx *= 0.03125f; cy *= 0.03125f; cz *= 0.03125f;
    if (lane == 0) {
        centers_out[3 * p]     = cx;
        centers_out[3 * p + 1] = cy;
        centers_out[3 * p + 2] = cz;
    }

    const float lx = q.x - cx, ly = q.y - cy, lz = q.z - cz;
    float c00 = lx * lx, c01 = lx * ly, c02 = lx * lz;
    float c11 = ly * ly, c12 = ly * lz, c22 = lz * lz;
#pragma unroll
    for (int off = 16; off; off >>= 1) {
        c00 += __shfl_xor_sync(0xffffffffu, c00, off);
        c01 += __shfl_xor_sync(0xffffffffu, c01, off);
        c02 += __shfl_xor_sync(0xffffffffu, c02, off);
        c11 += __shfl_xor_sync(0xffffffffu, c11, off);
        c12 += __shfl_xor_sync(0xffffffffu, c12, off);
        c22 += __shfl_xor_sync(0xffffffffu, c22, off);
    }
    if (lane == 0) {
        float A[6] = {c00 * 0.03125f, c01 * 0.03125f, c02 * 0.03125f,
                      c11 * 0.03125f, c12 * 0.03125f, c22 * 0.03125f};
        float V[3][3];
        eigh3(A, V);
        g_frame[p * 3 + 0] = make_float4(cx, cy, cz, V[0][0]);
        g_frame[p * 3 + 1] = make_float4(V[0][1], V[0][2], V[1][0], V[1][1]);
        g_frame[p * 3 + 2] = make_float4(V[1][2], V[2][0], V[2][1], V[2][2]);
    }
}

// ---------------------------------------------------------------------------
// Kernel 3: conv — one warp per point (R12 version, 28.3us)
// ---------------------------------------------------------------------------
__global__ __launch_bounds__(128, 8)
void conv_kernel(const float* __restrict__ chan,
                 float* __restrict__ out) {
    const int tid = threadIdx.x;
    const int lane = tid & 31;
    const int wid = tid >> 5;
    const int p = blockIdx.x * 4 + wid;

    __shared__ float s_basis[4][32][28];
    __shared__ float s_G[4][448];
    __shared__ float s_feat[4][32][16];

    const int nb = g_nbr[p * KNN + lane];
    const float4 q = g_posq[nb];

    {
        const float4* fr = (const float4*)(chan + nb * CIN);
        float4 f0 = fr[0], f1 = fr[1], f2 = fr[2], f3 = fr[3];
        float4* sf = (float4*)&s_feat[wid][lane][0];
        sf[0] = f0; sf[1] = f1; sf[2] = f2; sf[3] = f3;
    }

    const float4 f0 = __ldg(&g_frame[p * 3 + 0]);
    const float4 f1 = __ldg(&g_frame[p * 3 + 1]);
    const float4 f2 = __ldg(&g_frame[p * 3 + 2]);
    const float cx = f0.x, cy = f0.y, cz = f0.z;
    const float v00 = f0.w, v01 = f1.x, v02 = f1.y;
    const float v10 = f1.z, v11 = f1.w, v12 = f2.x;
    const float v20 = f2.y, v21 = f2.z, v22 = f2.w;

    const float lx = q.x - cx, ly = q.y - cy, lz = q.z - cz;

    {
        float x = lx * v00 + ly * v10 + lz * v20;
        float y = lx * v01 + ly * v11 + lz * v21;
        float z = lx * v02 + ly * v12 + lz * v22;
        float r = sqrtf(x * x + y * y + z * z);
        float ct = z / (r + 1e-8f);
        ct = fminf(fmaxf(ct, -1.f + 1e-6f), 1.f - 1e-6f);
        float theta = acosf(ct);
        float phi = atan2f(y, x);
        float rb[3] = {1.f, r, r * r};
        float tb[3] = {1.f, cosf(theta), cosf(2.f * theta)};
        float pb[3] = {1.f, cosf(phi), cosf(2.f * phi)};
#pragma unroll
        for (int n = 0; n < 3; ++n)
#pragma unroll
            for (int l = 0; l < 3; ++l)
#pragma unroll
                for (int m = 0; m < 3; ++m)
                    s_basis[wid][lane][n * 9 + l * 3 + m] = (rb[n] * tb[l]) * pb[m];
        s_basis[wid][lane][27] = 0.f;
    }
    __syncwarp();

    {
        const int c = lane >> 1;
        const int half = lane & 1;
        float acc[16];
#pragma unroll
        for (int i = 0; i < 16; ++i) acc[i] = 0.f;

#pragma unroll 8
        for (int k = 0; k < KNN; ++k) {
            float fv = s_feat[wid][k][c];
            const float* row = &s_basis[wid][k][0];
            if (half == 0) {
                float4 b0 = *(const float4*)(row);
                float4 b1 = *(const float4*)(row + 4);
                float4 b2 = *(const float4*)(row + 8);
                float4 b3 = *(const float4*)(row + 12);
                acc[0]  += b0.x * fv; acc[1]  += b0.y * fv; acc[2]  += b0.z * fv; acc[3]  += b0.w * fv;
                acc[4]  += b1.x * fv; acc[5]  += b1.y * fv; acc[6]  += b1.z * fv; acc[7]  += b1.w * fv;
                acc[8]  += b2.x * fv; acc[9]  += b2.y * fv; acc[10] += b2.z * fv; acc[11] += b2.w * fv;
                acc[12] += b3.x * fv; acc[13] += b3.y * fv; acc[14] += b3.z * fv; acc[15] += b3.w * fv;
            } else {
                float4 b0 = *(const float4*)(row + 16);
                float4 b1 = *(const float4*)(row + 20);
                float4 b2 = *(const float4*)(row + 24);
                acc[0]  += b0.x * fv; acc[1]  += b0.y * fv; acc[2]  += b0.z * fv; acc[3]  += b0.w * fv;
                acc[4]  += b1.x * fv; acc[5]  += b1.y * fv; acc[6]  += b1.z * fv; acc[7]  += b1.w * fv;
                acc[8]  += b2.x * fv; acc[9]  += b2.y * fv; acc[10] += b2.z * fv;
            }
        }
        if (half == 0) {
#pragma unroll
            for (int i = 0; i < 16; ++i) s_G[wid][c * 27 + i] = acc[i];
        } else {
#pragma unroll
            for (int i = 0; i < 11; ++i) s_G[wid][c * 27 + 16 + i] = acc[i];
        }
    }
    __syncwarp();

    {
        float a0 = 0.f, a1 = 0.f, a2 = 0.f, a3 = 0.f;
        const float* gT = g_coefT + lane * 4;
        const float* gw = &s_G[wid][0];
#pragma unroll 8
        for (int t = 0; t < 108; ++t) {
            float4 cf = *(const float4*)(gT + t * 128);
            float4 gv = *(const float4*)(gw + t * 4);
            a0 += cf.x * gv.x;
            a1 += cf.y * gv.y;
            a2 += cf.z * gv.z;
            a3 += cf.w * gv.w;
        }
        out[p * COUT + lane] = (a0 + a1) + (a2 + a3);
    }
}

extern "C" void kernel_launch(void* const* d_in, const int* in_sizes, int n_in,
                              void* d_out, int out_size) {
    const float* pos  = (const float*)d_in[0];
    const float* chan = (const float*)d_in[1];
    const float* coef = (const float*)d_in[3];

    float* d_outf = (float*)d_out;
    float* centers_ptr;
    float* out_ptr;
    if (out_size == NP * 3 + NP * COUT) {
        centers_ptr = d_outf;
        out_ptr     = d_outf + NP * 3;
    } else if (out_size == NP * COUT) {
        cudaGetSymbolAddress((void**)&centers_ptr, g_cscratch);
        out_ptr = d_outf;
    } else {
        centers_ptr = d_outf;
        cudaGetSymbolAddress((void**)&out_ptr, g_oscratch);
    }

    setup_kernel<<<54, 256>>>(pos, coef);
    knn_kernel<<<NP / QB, 256>>>();
    frame_kernel<<<NP / 4, 128>>>(centers_ptr);
    conv_kernel<<<NP / 4, 128>>>(chan, out_ptr);
}

// round 15
// speedup vs baseline: 1.2339x; 1.0840x over previous
#include <cuda_runtime.h>
#include <cuda_bf16.h>

#define NP   4096
#define KNN  32
#define CIN  16
#define COUT 32
#define NB   27
#define NG   432
#define QB   8        // queries per knn block
#define SCAP 384      // survivor cap per query

__device__ float4 g_posq[NP];
__device__ int    g_nbr[NP * KNN];
__device__ float  g_coefT[108 * 128];     // [j/4][o][j%4]
__device__ float4 g_frame[NP * 3];        // (cx,cy,cz,V00),(V01,V02,V10,V11),(V12,V20,V21,V22)
__device__ float  g_cscratch[NP * 3];
__device__ float  g_oscratch[NP * COUT];

// ---------------------------------------------------------------------------
// LAPACK fp32 helpers (LAPACK >= 3.10 conventions) — validated R2..R13.
// ---------------------------------------------------------------------------
__device__ __forceinline__ float slapy2f(float x, float y) {
    float xa = fabsf(x), ya = fabsf(y);
    float w = fmaxf(xa, ya), z = fminf(xa, ya);
    if (z == 0.f) return w;
    float t = z / w;
    return w * sqrtf(1.f + t * t);
}

__device__ __forceinline__ void slartgf(float f, float g, float* c, float* s, float* r) {
    if (g == 0.f)      { *c = 1.f; *s = 0.f; *r = f; }
    else if (f == 0.f) { *c = 0.f; *s = (g > 0.f) ? 1.f : -1.f; *r = fabsf(g); }
    else {
        float d = sqrtf(f * f + g * g);
        float p = 1.f / d;
        *c = fabsf(f) * p;
        *s = g * copysignf(p, f);
        *r = copysignf(d, f);
    }
}

__device__ void slaev2f(float a, float b, float c, float* rt1, float* rt2,
                        float* cs1, float* sn1) {
    float sm = a + c, df = a - c;
    float adf = fabsf(df);
    float tb = b + b, ab = fabsf(tb);
    float acmx, acmn;
    if (fabsf(a) > fabsf(c)) { acmx = a; acmn = c; } else { acmx = c; acmn = a; }
    float rt;
    if (adf > ab)      { float t = ab / adf; rt = adf * sqrtf(1.f + t * t); }
    else if (adf < ab) { float t = adf / ab; rt = ab * sqrtf(1.f + t * t); }
    else               rt = ab * sqrtf(2.f);
    int sgn1;
    if (sm < 0.f)      { *rt1 = 0.5f * (sm - rt); sgn1 = -1;
                         *rt2 = (acmx / *rt1) * acmn - (b / *rt1) * b; }
    else if (sm > 0.f) { *rt1 = 0.5f * (sm + rt); sgn1 = 1;
                         *rt2 = (acmx / *rt1) * acmn - (b / *rt1) * b; }
    else               { *rt1 = 0.5f * rt; *rt2 = -0.5f * rt; sgn1 = 1; }
    float cs; int sgn2;
    if (df >= 0.f) { cs = df + rt; sgn2 = 1; } else { cs = df - rt; sgn2 = -1; }
    float acs = fabsf(cs);
    if (acs > ab) {
        float ct = -tb / cs;
        *sn1 = 1.f / sqrtf(1.f + ct * ct);
        *cs1 = ct * *sn1;
    } else {
        if (ab == 0.f) { *cs1 = 1.f; *sn1 = 0.f; }
        else {
            float tn = -cs / tb;
            *cs1 = 1.f / sqrtf(1.f + tn * tn);
            *sn1 = tn * *cs1;
        }
    }
    if (sgn1 == sgn2) { float tn = *cs1; *cs1 = -*sn1; *sn1 = tn; }
}

// Register-resident ssteqr('I', n=3) — validated R13 (rel_err 3.0e-6).
__device__ void ssteqr3_reg(float D1, float D2, float D3, float E1, float E2,
                            float V[3][3]) {
    const float eps = 5.9604645e-08f, eps2 = eps * eps, safmin = 1.17549435e-38f;
    const int n = 3, nmaxit = 90;
    float d1_ = D1, d2_ = D2, d3_ = D3;
    float e1_ = E1, e2_ = E2;
    float z00 = 1.f, z01 = 0.f, z02 = 0.f;
    float z10 = 0.f, z11 = 1.f, z12 = 0.f;
    float z20 = 0.f, z21 = 0.f, z22 = 1.f;
    float wc1_ = 0.f, wc2_ = 0.f, ws1_ = 0.f, ws2_ = 0.f;

    auto GETD = [&](int i) -> float { return i == 1 ? d1_ : (i == 2 ? d2_ : d3_); };
    auto SETD = [&](int i, float v) { if (i == 1) d1_ = v; else if (i == 2) d2_ = v; else d3_ = v; };
    auto GETE = [&](int i) -> float { return i == 1 ? e1_ : e2_; };
    auto SETE = [&](int i, float v) { if (i == 1) e1_ = v; else e2_ = v; };
    auto GETWC = [&](int i) -> float { return i == 1 ? wc1_ : wc2_; };
    auto SETWC = [&](int i, float v) { if (i == 1) wc1_ = v; else wc2_ = v; };
    auto GETWS = [&](int i) -> float { return i == 1 ? ws1_ : ws2_; };
    auto SETWS = [&](int i, float v) { if (i == 1) ws1_ = v; else ws2_ = v; };
    auto ZROT = [&](int hi, float cc, float ss) {
        if (hi == 1) {
            float t;
            t = z01; z01 = cc * t - ss * z00; z00 = ss * t + cc * z00;
            t = z11; z11 = cc * t - ss * z10; z10 = ss * t + cc * z10;
            t = z21; z21 = cc * t - ss * z20; z20 = ss * t + cc * z20;
        } else {
            float t;
            t = z02; z02 = cc * t - ss * z01; z01 = ss * t + cc * z01;
            t = z12; z12 = cc * t - ss * z11; z11 = ss * t + cc * z11;
            t = z22; z22 = cc * t - ss * z21; z21 = ss * t + cc * z21;
        }
    };
    auto ZSWAP = [&](int a, int b) {
        float t;
        if (a == 0 && b == 1) {
            t = z00; z00 = z01; z01 = t;
            t = z10; z10 = z11; z11 = t;
            t = z20; z20 = z21; z21 = t;
        } else if (a == 0) {
            t = z00; z00 = z02; z02 = t;
            t = z10; z10 = z12; z12 = t;
            t = z20; z20 = z22; z22 = t;
        } else {
            t = z01; z01 = z02; z02 = t;
            t = z11; z11 = z12; z12 = t;
            t = z21; z21 = z22; z22 = t;
        }
    };

    int jtot = 0, l1 = 1;

    while (l1 <= n) {
        if (l1 > 1) SETE(l1 - 1, 0.f);
        int m = n;
        for (int mm = l1; mm <= n - 1; ++mm) {
            float tst = fabsf(GETE(mm));
            if (tst == 0.f) { m = mm; break; }
            if (tst <= (sqrtf(fabsf(GETD(mm))) * sqrtf(fabsf(GETD(mm + 1)))) * eps) {
                SETE(mm, 0.f); m = mm; break;
            }
        }
        int l = l1;
        int lsv = l, lend = m, lendsv = lend;
        l1 = m + 1;
        if (lend == l) continue;
        if (fabsf(GETD(lend)) < fabsf(GETD(l))) { lend = lsv; l = lendsv; }

        if (lend > l) {
            for (;;) {
                int mq = lend;
                if (l != lend) {
                    for (int mi = l; mi <= lend - 1; ++mi) {
                        float tst = GETE(mi) * GETE(mi);
                        if (tst <= (eps2 * fabsf(GETD(mi))) * fabsf(GETD(mi + 1)) + safmin) {
                            mq = mi; break;
                        }
                    }
                }
                if (mq < lend) SETE(mq, 0.f);
                float p = GETD(l);
                if (mq == l) { SETD(l, p); if (++l <= lend) continue; break; }
                if (mq == l + 1) {
                    float rt1, rt2, c, s;
                    slaev2f(GETD(l), GETE(l), GETD(l + 1), &rt1, &rt2, &c, &s);
                    ZROT(l, c, s);
                    SETD(l, rt1); SETD(l + 1, rt2); SETE(l, 0.f);
                    l += 2;
                    if (l <= lend) continue;
                    break;
                }
                if (jtot == nmaxit) break;
                ++jtot;
                float g = (GETD(l + 1) - p) / (2.f * GETE(l));
                float r = slapy2f(g, 1.f);
                g = GETD(mq) - p + (GETE(l) / (g + copysignf(r, g)));
                float s = 1.f, c = 1.f; p = 0.f;
                for (int i = mq - 1; i >= l; --i) {
                    float f = s * GETE(i), b = c * GETE(i);
                    slartgf(g, f, &c, &s, &r);
                    if (i != mq - 1) SETE(i + 1, r);
                    g = GETD(i + 1) - p;
                    r = (GETD(i) - g) * s + 2.f * c * b;
                    p = s * r;
                    SETD(i + 1, g + p);
                    g = c * r - b;
                    SETWC(i, c); SETWS(i, -s);
                }
                for (int j = mq - l; j >= 1; --j) {
                    int hi = l + j - 1;
                    ZROT(hi, GETWC(hi), GETWS(hi));
                }
                SETD(l, GETD(l) - p);
                SETE(l, g);
            }
        } else {
            for (;;) {
                int mq = lend;
                if (l != lend) {
                    for (int mi = l; mi >= lend + 1; --mi) {
                        float tst = GETE(mi - 1) * GETE(mi - 1);
                        if (tst <= (eps2 * fabsf(GETD(mi))) * fabsf(GETD(mi - 1)) + safmin) {
                            mq = mi; break;
                        }
                    }
                }
                if (mq > lend) SETE(mq - 1, 0.f);
                float p = GETD(l);
                if (mq == l) { SETD(l, p); if (--l >= lend) continue; break; }
                if (mq == l - 1) {
                    float rt1, rt2, c, s;
                    slaev2f(GETD(l - 1), GETE(l - 1), GETD(l), &rt1, &rt2, &c, &s);
                    ZROT(l - 1, c, s);
                    SETD(l - 1, rt1); SETD(l, rt2); SETE(l - 1, 0.f);
                    l -= 2;
                    if (l >= lend) continue;
                    break;
                }
                if (jtot == nmaxit) break;
                ++jtot;
                float g = (GETD(l - 1) - p) / (2.f * GETE(l - 1));
                float r = slapy2f(g, 1.f);
                g = GETD(mq) - p + (GETE(l - 1) / (g + copysignf(r, g)));
                float s = 1.f, c = 1.f; p = 0.f;
                for (int i = mq; i <= l - 1; ++i) {
                    float f = s * GETE(i), b = c * GETE(i);
                    slartgf(g, f, &c, &s, &r);
                    if (i != mq) SETE(i - 1, r);
                    g = GETD(i) - p;
                    r = (GETD(i + 1) - g) * s + 2.f * c * b;
                    p = s * r;
                    SETD(i, g + p);
                    g = c * r - b;
                    SETWC(i, c); SETWS(i, s);
                }
                for (int j = 1; j <= l - mq; ++j) {
                    int hi = mq + j - 1;
                    ZROT(hi, GETWC(hi), GETWS(hi));
                }
                SETD(l, GETD(l) - p);
                SETE(l - 1, g);
            }
        }
    }
    for (int ii = 2; ii <= n; ++ii) {
        int i = ii - 1, k = i;
        float p = GETD(i);
        for (int j = ii; j <= n; ++j) if (GETD(j) < p) { k = j; p = GETD(j); }
        if (k != i) {
            SETD(k, GETD(i)); SETD(i, p);
            ZSWAP(i - 1, k - 1);
        }
    }

    V[0][0] = z00; V[0][1] = z01; V[0][2] = z02;
    V[1][0] = z10; V[1][1] = z11; V[1][2] = z12;
    V[2][0] = z20; V[2][1] = z21; V[2][2] = z22;
}

__device__ void eigh3(const float A[6], float V[3][3]) {
    float a00 = A[0], a10 = A[1], a20 = A[2], a11 = A[3], a21 = A[4], a22 = A[5];
    float tau = 0.f, v2 = 0.f, e0, e1, d1 = a11, d2v = a22;
    float xnorm = fabsf(a20);
    if (xnorm == 0.f) { tau = 0.f; e0 = a10; e1 = a21; }
    else {
        float alpha = a10;
        float beta = -copysignf(slapy2f(alpha, xnorm), alpha);
        tau = (beta - alpha) / beta;
        v2 = a20 * (1.f / (alpha - beta));
        e0 = beta;
        float w0 = tau * a11 + tau * (a21 * v2);
        float w1 = tau * a21 + (tau * v2) * a22;
        float aw = -0.5f * tau * (w0 + w1 * v2);
        w0 += aw; w1 += aw * v2;
        d1  = (a11 - w0) - w0;
        e1  = (a21 - v2 * w0) - w1;
        d2v = (a22 - v2 * w1) - w1 * v2;
    }
    ssteqr3_reg(a00, d1, d2v, e0, e1, V);
    if (tau != 0.f) {
        for (int j = 0; j < 3; ++j) {
            float s = V[1][j] + v2 * V[2][j];
            V[1][j] -= tau * s;
            V[2][j] -= tau * v2 * s;
        }
    }
}

// ---------------------------------------------------------------------------
__device__ __forceinline__ unsigned long long warp_min64(unsigned long long k) {
    unsigned hi = (unsigned)(k >> 32), lo = (unsigned)k;
    unsigned mhi = __reduce_min_sync(0xffffffffu, hi);
    unsigned lo2 = (hi == mhi) ? lo : 0xffffffffu;
    unsigned mlo = __reduce_min_sync(0xffffffffu, lo2);
    return ((unsigned long long)mhi << 32) | mlo;
}

__device__ __forceinline__ unsigned f2u(float f) {
    int i = __float_as_int(f);
    return (i < 0) ? ~(unsigned)i : ((unsigned)i | 0x80000000u);
}

// prep + coef transpose (destination-major -> coalesced writes)
__global__ void setup_kernel(const float* __restrict__ pos,
                             const float* __restrict__ coef) {
    int i = blockIdx.x * blockDim.x + threadIdx.x;
    if (i < NP) {
        float x = pos[3 * i], y = pos[3 * i + 1], z = pos[3 * i + 2];
        g_posq[i] = make_float4(x, y, z, x * x + y * y + z * z);
    }
    if (i < COUT * NG) {
        int t = i >> 7;
        int rem = i & 127;
        int o = rem >> 2, m2 = rem & 3;
        g_coefT[i] = coef[o * NG + t * 4 + m2];
    }
}

// ---------------------------------------------------------------------------
// Kernel 1: exact kNN, 8 queries per block (R12/R13 version — unchanged)
// ---------------------------------------------------------------------------
__global__ __launch_bounds__(256)
void knn_kernel() {
    const int tid = threadIdx.x;
    const int lane = tid & 31;
    const int wid = tid >> 5;
    const int qbase = blockIdx.x * QB;

    __shared__ unsigned long long s_surv[QB][SCAP];
    __shared__ unsigned s_b4[QB][8];
    __shared__ int s_cnt[QB];

    if (tid < QB) s_cnt[tid] = 0;

    float4 pq[QB];
#pragma unroll
    for (int q = 0; q < QB; ++q) pq[q] = g_posq[qbase + q];

    float mn[QB];
#pragma unroll
    for (int q = 0; q < QB; ++q) mn[q] = __int_as_float(0x7f800000);

#pragma unroll 4
    for (int j = 0; j < 16; ++j) {
        int cand = tid + (j << 8);
        float4 cq = g_posq[cand];
#pragma unroll
        for (int q = 0; q < QB; ++q) {
            float dot = pq[q].x * cq.x + pq[q].y * cq.y + pq[q].z * cq.z;
            float d2 = (pq[q].w + cq.w) - 2.f * dot;
            mn[q] = fminf(mn[q], d2);
        }
    }

#pragma unroll
    for (int q = 0; q < QB; ++q) {
        unsigned h = f2u(mn[q]), w4 = 0;
#pragma unroll
        for (int r = 0; r < 4; ++r) {
            w4 = __reduce_min_sync(0xffffffffu, h);
            if (h == w4) h = 0xffffffffu;
        }
        if (lane == 0) s_b4[q][wid] = w4;
    }
    __syncthreads();

    float Bf[QB];
#pragma unroll
    for (int q = 0; q < QB; ++q) {
        unsigned B = s_b4[q][0];
#pragma unroll
        for (int w = 1; w < 8; ++w) B = max(B, s_b4[q][w]);
        int bi = (B & 0x80000000u) ? (int)(B & 0x7fffffffu) : (int)~B;
        Bf[q] = __int_as_float(bi);
    }

#pragma unroll
    for (int q = 0; q < QB; ++q) {
        if (mn[q] <= Bf[q]) {
#pragma unroll 4
            for (int j = 0; j < 16; ++j) {
                int cand = tid + (j << 8);
                float4 cq = g_posq[cand];
                float dot = pq[q].x * cq.x + pq[q].y * cq.y + pq[q].z * cq.z;
                float d2 = (pq[q].w + cq.w) - 2.f * dot;
                if (d2 <= Bf[q]) {
                    unsigned u = f2u(d2);
                    int pos = atomicAdd(&s_cnt[q], 1);
                    if (pos < SCAP)
                        s_surv[q][pos] = ((unsigned long long)u << 32) | (unsigned)cand;
                }
            }
        }
    }
    __syncthreads();

    {
        const int q = wid;
        int S = s_cnt[q] < SCAP ? s_cnt[q] : SCAP;
        if (S <= 256) {
            unsigned long long k0, k1, k2, k3, k4, k5, k6, k7;
            k0 = (lane        < S) ? s_surv[q][lane]        : ~0ULL;
            k1 = (lane +  32  < S) ? s_surv[q][lane +  32]  : ~0ULL;
            k2 = (lane +  64  < S) ? s_surv[q][lane +  64]  : ~0ULL;
            k3 = (lane +  96  < S) ? s_surv[q][lane +  96]  : ~0ULL;
            k4 = (lane + 128  < S) ? s_surv[q][lane + 128]  : ~0ULL;
            k5 = (lane + 160  < S) ? s_surv[q][lane + 160]  : ~0ULL;
            k6 = (lane + 192  < S) ? s_surv[q][lane + 192]  : ~0ULL;
            k7 = (lane + 224  < S) ? s_surv[q][lane + 224]  : ~0ULL;
#define CE(a, b) { if (a > b) { unsigned long long t = a; a = b; b = t; } }
            CE(k0, k1) CE(k2, k3) CE(k4, k5) CE(k6, k7)
            CE(k0, k2) CE(k1, k3) CE(k1, k2)
            CE(k4, k6) CE(k5, k7) CE(k5, k6)
            CE(k0, k4) CE(k1, k5) CE(k2, k6) CE(k3, k7)
            CE(k2, k4) CE(k3, k5)
            CE(k1, k2) CE(k3, k4) CE(k5, k6)
#undef CE
#pragma unroll
            for (int r = 0; r < KNN; ++r) {
                unsigned long long w = warp_min64(k0);
                if (lane == 0) g_nbr[(qbase + q) * KNN + r] = (int)(w & 0xffffffffu);
                if (k0 == w) {
                    k0 = k1; k1 = k2; k2 = k3; k3 = k4;
                    k4 = k5; k5 = k6; k6 = k7; k7 = ~0ULL;
                }
            }
        } else {
            for (int r = 0; r < KNN; ++r) {
                unsigned long long m = ~0ULL; int mi = -1;
                for (int i = lane; i < S; i += 32) {
                    unsigned long long v = s_surv[q][i];
                    if (v < m) { m = v; mi = i; }
                }
                unsigned long long w = warp_min64(m);
                if (m == w && mi >= 0) s_surv[q][mi] = ~0ULL;
                if (lane == 0) g_nbr[(qbase + q) * KNN + r] = (int)(w & 0xffffffffu);
            }
        }
    }
}

// ---------------------------------------------------------------------------
// Kernel 2: frames — one warp per point (R13 version — unchanged)
// ---------------------------------------------------------------------------
__global__ __launch_bounds__(128)
void frame_kernel(float* __restrict__ centers_out) {
    const int tid = threadIdx.x;
    const int lane = tid & 31;
    const int wid = tid >> 5;
    const int p = blockIdx.x * 4 + wid;

    const int nb = g_nbr[p * KNN + lane];
    const float4 q = g_posq[nb];

    float cx = q.x, cy = q.y, cz = q.z;
#pragma unroll
    for (int off = 16; off; off >>= 1) {
        cx += __shfl_xor_sync(0xffffffffu, cx, off);
        cy += __shfl_xor_sync(0xffffffffu, cy, off);
        cz += __shfl_xor_sync(0xffffffffu, cz, off);
    }
    cx *= 0.03125f; cy *= 0.03125f; cz *= 0.03125f;
    if (lane == 0) {
        centers_out[3 * p]     = cx;
        centers_out[3 * p + 1] = cy;
        centers_out[3 * p + 2] = cz;
    }

    const float lx = q.x - cx, ly = q.y - cy, lz = q.z - cz;
    float c00 = lx * lx, c01 = lx * ly, c02 = lx * lz;
    float c11 = ly * ly, c12 = ly * lz, c22 = lz * lz;
#pragma unroll
    for (int off = 16; off; off >>= 1) {
        c00 += __shfl_xor_sync(0xffffffffu, c00, off);
        c01 += __shfl_xor_sync(0xffffffffu, c01, off);
        c02 += __shfl_xor_sync(0xffffffffu, c02, off);
        c11 += __shfl_xor_sync(0xffffffffu, c11, off);
        c12 += __shfl_xor_sync(0xffffffffu, c12, off);
        c22 += __shfl_xor_sync(0xffffffffu, c22, off);
    }
    if (lane == 0) {
        float A[6] = {c00 * 0.03125f, c01 * 0.03125f, c02 * 0.03125f,
                      c11 * 0.03125f, c12 * 0.03125f, c22 * 0.03125f};
        float V[3][3];
        eigh3(A, V);
        g_frame[p * 3 + 0] = make_float4(cx, cy, cz, V[0][0]);
        g_frame[p * 3 + 1] = make_float4(V[0][1], V[0][2], V[1][0], V[1][1]);
        g_frame[p * 3 + 2] = make_float4(V[1][2], V[2][0], V[2][1], V[2][2]);
    }
}

// ---------------------------------------------------------------------------
// Kernel 3: conv — phase A one warp per point (unchanged numerics for G);
// phase B amortizes coefT across the block's 4 points (4x less L1 traffic).
// ---------------------------------------------------------------------------
__global__ __launch_bounds__(128, 7)
void conv_kernel(const float* __restrict__ chan,
                 float* __restrict__ out) {
    const int tid = threadIdx.x;
    const int lane = tid & 31;
    const int wid = tid >> 5;
    const int p = blockIdx.x * 4 + wid;

    __shared__ float s_basis[4][32][28];
    __shared__ float s_G[4][448];
    __shared__ float s_feat[4][32][16];   // dead after phase A; re-used as s_po

    const int nb = g_nbr[p * KNN + lane];
    const float4 q = g_posq[nb];

    {
        const float4* fr = (const float4*)(chan + nb * CIN);
        float4 f0 = fr[0], f1 = fr[1], f2 = fr[2], f3 = fr[3];
        float4* sf = (float4*)&s_feat[wid][lane][0];
        sf[0] = f0; sf[1] = f1; sf[2] = f2; sf[3] = f3;
    }

    const float4 f0 = __ldg(&g_frame[p * 3 + 0]);
    const float4 f1 = __ldg(&g_frame[p * 3 + 1]);
    const float4 f2 = __ldg(&g_frame[p * 3 + 2]);
    const float cx = f0.x, cy = f0.y, cz = f0.z;
    const float v00 = f0.w, v01 = f1.x, v02 = f1.y;
    const float v10 = f1.z, v11 = f1.w, v12 = f2.x;
    const float v20 = f2.y, v21 = f2.z, v22 = f2.w;

    const float lx = q.x - cx, ly = q.y - cy, lz = q.z - cz;

    {
        float x = lx * v00 + ly * v10 + lz * v20;
        float y = lx * v01 + ly * v11 + lz * v21;
        float z = lx * v02 + ly * v12 + lz * v22;
        float r = sqrtf(x * x + y * y + z * z);
        float ct = z / (r + 1e-8f);
        ct = fminf(fmaxf(ct, -1.f + 1e-6f), 1.f - 1e-6f);
        float theta = acosf(ct);
        float phi = atan2f(y, x);
        float rb[3] = {1.f, r, r * r};
        float tb[3] = {1.f, cosf(theta), cosf(2.f * theta)};
        float pb[3] = {1.f, cosf(phi), cosf(2.f * phi)};
#pragma unroll
        for (int n = 0; n < 3; ++n)
#pragma unroll
            for (int l = 0; l < 3; ++l)
#pragma unroll
                for (int m = 0; m < 3; ++m)
                    s_basis[wid][lane][n * 9 + l * 3 + m] = (rb[n] * tb[l]) * pb[m];
        s_basis[wid][lane][27] = 0.f;
    }
    __syncwarp();

    // phase 4: G[c*27+nlm] = sum_k basis[k][nlm]*feat[k][c]  (unchanged)
    {
        const int c = lane >> 1;
        const int half = lane & 1;
        float acc[16];
#pragma unroll
        for (int i = 0; i < 16; ++i) acc[i] = 0.f;

#pragma unroll 8
        for (int k = 0; k < KNN; ++k) {
            float fv = s_feat[wid][k][c];
            const float* row = &s_basis[wid][k][0];
            if (half == 0) {
                float4 b0 = *(const float4*)(row);
                float4 b1 = *(const float4*)(row + 4);
                float4 b2 = *(const float4*)(row + 8);
                float4 b3 = *(const float4*)(row + 12);
                acc[0]  += b0.x * fv; acc[1]  += b0.y * fv; acc[2]  += b0.z * fv; acc[3]  += b0.w * fv;
                acc[4]  += b1.x * fv; acc[5]  += b1.y * fv; acc[6]  += b1.z * fv; acc[7]  += b1.w * fv;
                acc[8]  += b2.x * fv; acc[9]  += b2.y * fv; acc[10] += b2.z * fv; acc[11] += b2.w * fv;
                acc[12] += b3.x * fv; acc[13] += b3.y * fv; acc[14] += b3.z * fv; acc[15] += b3.w * fv;
            } else {
                float4 b0 = *(const float4*)(row + 16);
                float4 b1 = *(const float4*)(row + 20);
                float4 b2 = *(const float4*)(row + 24);
                acc[0]  += b0.x * fv; acc[1]  += b0.y * fv; acc[2]  += b0.z * fv; acc[3]  += b0.w * fv;
                acc[4]  += b1.x * fv; acc[5]  += b1.y * fv; acc[6]  += b1.z * fv; acc[7]  += b1.w * fv;
                acc[8]  += b2.x * fv; acc[9]  += b2.y * fv; acc[10] += b2.z * fv;
            }
        }
        if (half == 0) {
#pragma unroll
            for (int i = 0; i < 16; ++i) s_G[wid][c * 27 + i] = acc[i];
        } else {
#pragma unroll
            for (int i = 0; i < 11; ++i) s_G[wid][c * 27 + 16 + i] = acc[i];
        }
    }
    __syncthreads();    // all 4 points' G ready; s_feat now dead

    // phase 5 (coef-amortized): warp `wid` handles t-chunk [27*wid, 27*wid+27)
    // for ALL 4 points. coefT read once per block instead of once per point.
    float* s_po = &s_feat[0][0][0];     // alias: [(chunkwarp*4 + pt)*32 + o]
    {
        float a0 = 0.f, a1 = 0.f, a2 = 0.f, a3 = 0.f;
        const float* gT = g_coefT + lane * 4;
        const int t0 = 27 * wid;
#pragma unroll 9
        for (int t = t0; t < t0 + 27; ++t) {
            float4 cf = *(const float4*)(gT + t * 128);
            float4 g0 = *(const float4*)(&s_G[0][t * 4]);
            float4 g1 = *(const float4*)(&s_G[1][t * 4]);
            float4 g2 = *(const float4*)(&s_G[2][t * 4]);
            float4 g3 = *(const float4*)(&s_G[3][t * 4]);
            a0 += cf.x * g0.x; a0 += cf.y * g0.y; a0 += cf.z * g0.z; a0 += cf.w * g0.w;
            a1 += cf.x * g1.x; a1 += cf.y * g1.y; a1 += cf.z * g1.z; a1 += cf.w * g1.w;
            a2 += cf.x * g2.x; a2 += cf.y * g2.y; a2 += cf.z * g2.z; a2 += cf.w * g2.w;
            a3 += cf.x * g3.x; a3 += cf.y * g3.y; a3 += cf.z * g3.z; a3 += cf.w * g3.w;
        }
        s_po[(wid * 4 + 0) * 32 + lane] = a0;
        s_po[(wid * 4 + 1) * 32 + lane] = a1;
        s_po[(wid * 4 + 2) * 32 + lane] = a2;
        s_po[(wid * 4 + 3) * 32 + lane] = a3;
    }
    __syncthreads();

    // phase 6: warp `wid` reduces the 4 chunk-partials for its own point
    {
        float r0 = s_po[(0 * 4 + wid) * 32 + lane];
        float r1 = s_po[(1 * 4 + wid) * 32 + lane];
        float r2 = s_po[(2 * 4 + wid) * 32 + lane];
        float r3 = s_po[(3 * 4 + wid) * 32 + lane];
        out[p * COUT + lane] = (r0 + r1) + (r2 + r3);
    }
}

extern "C" void kernel_launch(void* const* d_in, const int* in_sizes, int n_in,
                              void* d_out, int out_size) {
    const float* pos  = (const float*)d_in[0];
    const float* chan = (const float*)d_in[1];
    const float* coef = (const float*)d_in[3];

    float* d_outf = (float*)d_out;
    float* centers_ptr;
    float* out_ptr;
    if (out_size == NP * 3 + NP * COUT) {
        centers_ptr = d_outf;
        out_ptr     = d_outf + NP * 3;
    } else if (out_size == NP * COUT) {
        cudaGetSymbolAddress((void**)&centers_ptr, g_cscratch);
        out_ptr = d_outf;
    } else {
        centers_ptr = d_outf;
        cudaGetSymbolAddress((void**)&out_ptr, g_oscratch);
    }

    setup_kernel<<<54, 256>>>(pos, coef);
    knn_kernel<<<NP / QB, 256>>>();
    frame_kernel<<<NP / 4, 128>>>(centers_ptr);
    conv_kernel<<<NP / 4, 128>>>(chan, out_ptr);
}

// round 16
// speedup vs baseline: 1.2747x; 1.0331x over previous
#include <cuda_runtime.h>
#include <cuda_bf16.h>

#define NP   4096
#define KNN  32
#define CIN  16
#define COUT 32
#define NB   27
#define NG   432
#define QB   8        // queries per knn block
#define SCAP 384      // survivor cap per query

__device__ float4 g_posq[NP];
__device__ int    g_nbr[NP * KNN];
__device__ float  g_coefT[108 * 128];     // [j/4][o][j%4]
__device__ float4 g_frame[NP * 3];
__device__ float  g_cscratch[NP * 3];
__device__ float  g_oscratch[NP * COUT];

// ---------------------------------------------------------------------------
// LAPACK fp32 helpers (LAPACK >= 3.10 conventions) — validated R2..R14.
// ---------------------------------------------------------------------------
__device__ __forceinline__ float slapy2f(float x, float y) {
    float xa = fabsf(x), ya = fabsf(y);
    float w = fmaxf(xa, ya), z = fminf(xa, ya);
    if (z == 0.f) return w;
    float t = z / w;
    return w * sqrtf(1.f + t * t);
}

__device__ __forceinline__ void slartgf(float f, float g, float* c, float* s, float* r) {
    if (g == 0.f)      { *c = 1.f; *s = 0.f; *r = f; }
    else if (f == 0.f) { *c = 0.f; *s = (g > 0.f) ? 1.f : -1.f; *r = fabsf(g); }
    else {
        float d = sqrtf(f * f + g * g);
        float p = 1.f / d;
        *c = fabsf(f) * p;
        *s = g * copysignf(p, f);
        *r = copysignf(d, f);
    }
}

__device__ void slaev2f(float a, float b, float c, float* rt1, float* rt2,
                        float* cs1, float* sn1) {
    float sm = a + c, df = a - c;
    float adf = fabsf(df);
    float tb = b + b, ab = fabsf(tb);
    float acmx, acmn;
    if (fabsf(a) > fabsf(c)) { acmx = a; acmn = c; } else { acmx = c; acmn = a; }
    float rt;
    if (adf > ab)      { float t = ab / adf; rt = adf * sqrtf(1.f + t * t); }
    else if (adf < ab) { float t = adf / ab; rt = ab * sqrtf(1.f + t * t); }
    else               rt = ab * sqrtf(2.f);
    int sgn1;
    if (sm < 0.f)      { *rt1 = 0.5f * (sm - rt); sgn1 = -1;
                         *rt2 = (acmx / *rt1) * acmn - (b / *rt1) * b; }
    else if (sm > 0.f) { *rt1 = 0.5f * (sm + rt); sgn1 = 1;
                         *rt2 = (acmx / *rt1) * acmn - (b / *rt1) * b; }
    else               { *rt1 = 0.5f * rt; *rt2 = -0.5f * rt; sgn1 = 1; }
    float cs; int sgn2;
    if (df >= 0.f) { cs = df + rt; sgn2 = 1; } else { cs = df - rt; sgn2 = -1; }
    float acs = fabsf(cs);
    if (acs > ab) {
        float ct = -tb / cs;
        *sn1 = 1.f / sqrtf(1.f + ct * ct);
        *cs1 = ct * *sn1;
    } else {
        if (ab == 0.f) { *cs1 = 1.f; *sn1 = 0.f; }
        else {
            float tn = -cs / tb;
            *cs1 = 1.f / sqrtf(1.f + tn * tn);
            *sn1 = tn * *cs1;
        }
    }
    if (sgn1 == sgn2) { float tn = *cs1; *cs1 = -*sn1; *sn1 = tn; }
}

// Register-resident ssteqr('I', n=3) — validated R13/R14.
__device__ void ssteqr3_reg(float D1, float D2, float D3, float E1, float E2,
                            float V[3][3]) {
    const float eps = 5.9604645e-08f, eps2 = eps * eps, safmin = 1.17549435e-38f;
    const int n = 3, nmaxit = 90;
    float d1_ = D1, d2_ = D2, d3_ = D3;
    float e1_ = E1, e2_ = E2;
    float z00 = 1.f, z01 = 0.f, z02 = 0.f;
    float z10 = 0.f, z11 = 1.f, z12 = 0.f;
    float z20 = 0.f, z21 = 0.f, z22 = 1.f;
    float wc1_ = 0.f, wc2_ = 0.f, ws1_ = 0.f, ws2_ = 0.f;

    auto GETD = [&](int i) -> float { return i == 1 ? d1_ : (i == 2 ? d2_ : d3_); };
    auto SETD = [&](int i, float v) { if (i == 1) d1_ = v; else if (i == 2) d2_ = v; else d3_ = v; };
    auto GETE = [&](int i) -> float { return i == 1 ? e1_ : e2_; };
    auto SETE = [&](int i, float v) { if (i == 1) e1_ = v; else e2_ = v; };
    auto GETWC = [&](int i) -> float { return i == 1 ? wc1_ : wc2_; };
    auto SETWC = [&](int i, float v) { if (i == 1) wc1_ = v; else wc2_ = v; };
    auto GETWS = [&](int i) -> float { return i == 1 ? ws1_ : ws2_; };
    auto SETWS = [&](int i, float v) { if (i == 1) ws1_ = v; else ws2_ = v; };
    auto ZROT = [&](int hi, float cc, float ss) {
        if (hi == 1) {
            float t;
            t = z01; z01 = cc * t - ss * z00; z00 = ss * t + cc * z00;
            t = z11; z11 = cc * t - ss * z10; z10 = ss * t + cc * z10;
            t = z21; z21 = cc * t - ss * z20; z20 = ss * t + cc * z20;
        } else {
            float t;
            t = z02; z02 = cc * t - ss * z01; z01 = ss * t + cc * z01;
            t = z12; z12 = cc * t - ss * z11; z11 = ss * t + cc * z11;
            t = z22; z22 = cc * t - ss * z21; z21 = ss * t + cc * z21;
        }
    };
    auto ZSWAP = [&](int a, int b) {
        float t;
        if (a == 0 && b == 1) {
            t = z00; z00 = z01; z01 = t;
            t = z10; z10 = z11; z11 = t;
            t = z20; z20 = z21; z21 = t;
        } else if (a == 0) {
            t = z00; z00 = z02; z02 = t;
            t = z10; z10 = z12; z12 = t;
            t = z20; z20 = z22; z22 = t;
        } else {
            t = z01; z01 = z02; z02 = t;
            t = z11; z11 = z12; z12 = t;
            t = z21; z21 = z22; z22 = t;
        }
    };

    int jtot = 0, l1 = 1;

    while (l1 <= n) {
        if (l1 > 1) SETE(l1 - 1, 0.f);
        int m = n;
        for (int mm = l1; mm <= n - 1; ++mm) {
            float tst = fabsf(GETE(mm));
            if (tst == 0.f) { m = mm; break; }
            if (tst <= (sqrtf(fabsf(GETD(mm))) * sqrtf(fabsf(GETD(mm + 1)))) * eps) {
                SETE(mm, 0.f); m = mm; break;
            }
        }
        int l = l1;
        int lsv = l, lend = m, lendsv = lend;
        l1 = m + 1;
        if (lend == l) continue;
        if (fabsf(GETD(lend)) < fabsf(GETD(l))) { lend = lsv; l = lendsv; }

        if (lend > l) {
            for (;;) {
                int mq = lend;
                if (l != lend) {
                    for (int mi = l; mi <= lend - 1; ++mi) {
                        float tst = GETE(mi) * GETE(mi);
                        if (tst <= (eps2 * fabsf(GETD(mi))) * fabsf(GETD(mi + 1)) + safmin) {
                            mq = mi; break;
                        }
                    }
                }
                if (mq < lend) SETE(mq, 0.f);
                float p = GETD(l);
                if (mq == l) { SETD(l, p); if (++l <= lend) continue; break; }
                if (mq == l + 1) {
                    float rt1, rt2, c, s;
                    slaev2f(GETD(l), GETE(l), GETD(l + 1), &rt1, &rt2, &c, &s);
                    ZROT(l, c, s);
                    SETD(l, rt1); SETD(l + 1, rt2); SETE(l, 0.f);
                    l += 2;
                    if (l <= lend) continue;
                    break;
                }
                if (jtot == nmaxit) break;
                ++jtot;
                float g = (GETD(l + 1) - p) / (2.f * GETE(l));
                float r = slapy2f(g, 1.f);
                g = GETD(mq) - p + (GETE(l) / (g + copysignf(r, g)));
                float s = 1.f, c = 1.f; p = 0.f;
                for (int i = mq - 1; i >= l; --i) {
                    float f = s * GETE(i), b = c * GETE(i);
                    slartgf(g, f, &c, &s, &r);
                    if (i != mq - 1) SETE(i + 1, r);
                    g = GETD(i + 1) - p;
                    r = (GETD(i) - g) * s + 2.f * c * b;
                    p = s * r;
                    SETD(i + 1, g + p);
                    g = c * r - b;
                    SETWC(i, c); SETWS(i, -s);
                }
                for (int j = mq - l; j >= 1; --j) {
                    int hi = l + j - 1;
                    ZROT(hi, GETWC(hi), GETWS(hi));
                }
                SETD(l, GETD(l) - p);
                SETE(l, g);
            }
        } else {
            for (;;) {
                int mq = lend;
                if (l != lend) {
                    for (int mi = l; mi >= lend + 1; --mi) {
                        float tst = GETE(mi - 1) * GETE(mi - 1);
                        if (tst <= (eps2 * fabsf(GETD(mi))) * fabsf(GETD(mi - 1)) + safmin) {
                            mq = mi; break;
                        }
                    }
                }
                if (mq > lend) SETE(mq - 1, 0.f);
                float p = GETD(l);
                if (mq == l) { SETD(l, p); if (--l >= lend) continue; break; }
                if (mq == l - 1) {
                    float rt1, rt2, c, s;
                    slaev2f(GETD(l - 1), GETE(l - 1), GETD(l), &rt1, &rt2, &c, &s);
                    ZROT(l - 1, c, s);
                    SETD(l - 1, rt1); SETD(l, rt2); SETE(l - 1, 0.f);
                    l -= 2;
                    if (l >= lend) continue;
                    break;
                }
                if (jtot == nmaxit) break;
                ++jtot;
                float g = (GETD(l - 1) - p) / (2.f * GETE(l - 1));
                float r = slapy2f(g, 1.f);
                g = GETD(mq) - p + (GETE(l - 1) / (g + copysignf(r, g)));
                float s = 1.f, c = 1.f; p = 0.f;
                for (int i = mq; i <= l - 1; ++i) {
                    float f = s * GETE(i), b = c * GETE(i);
                    slartgf(g, f, &c, &s, &r);
                    if (i != mq) SETE(i - 1, r);
                    g = GETD(i) - p;
                    r = (GETD(i + 1) - g) * s + 2.f * c * b;
                    p = s * r;
                    SETD(i, g + p);
                    g = c * r - b;
                    SETWC(i, c); SETWS(i, s);
                }
                for (int j = 1; j <= l - mq; ++j) {
                    int hi = mq + j - 1;
                    ZROT(hi, GETWC(hi), GETWS(hi));
                }
                SETD(l, GETD(l) - p);
                SETE(l - 1, g);
            }
        }
    }
    for (int ii = 2; ii <= n; ++ii) {
        int i = ii - 1, k = i;
        float p = GETD(i);
        for (int j = ii; j <= n; ++j) if (GETD(j) < p) { k = j; p = GETD(j); }
        if (k != i) {
            SETD(k, GETD(i)); SETD(i, p);
            ZSWAP(i - 1, k - 1);
        }
    }

    V[0][0] = z00; V[0][1] = z01; V[0][2] = z02;
    V[1][0] = z10; V[1][1] = z11; V[1][2] = z12;
    V[2][0] = z20; V[2][1] = z21; V[2][2] = z22;
}

__device__ void eigh3(const float A[6], float V[3][3]) {
    float a00 = A[0], a10 = A[1], a20 = A[2], a11 = A[3], a21 = A[4], a22 = A[5];
    float tau = 0.f, v2 = 0.f, e0, e1, d1 = a11, d2v = a22;
    float xnorm = fabsf(a20);
    if (xnorm == 0.f) { tau = 0.f; e0 = a10; e1 = a21; }
    else {
        float alpha = a10;
        float beta = -copysignf(slapy2f(alpha, xnorm), alpha);
        tau = (beta - alpha) / beta;
        v2 = a20 * (1.f / (alpha - beta));
        e0 = beta;
        float w0 = tau * a11 + tau * (a21 * v2);
        float w1 = tau * a21 + (tau * v2) * a22;
        float aw = -0.5f * tau * (w0 + w1 * v2);
        w0 += aw; w1 += aw * v2;
        d1  = (a11 - w0) - w0;
        e1  = (a21 - v2 * w0) - w1;
        d2v = (a22 - v2 * w1) - w1 * v2;
    }
    ssteqr3_reg(a00, d1, d2v, e0, e1, V);
    if (tau != 0.f) {
        for (int j = 0; j < 3; ++j) {
            float s = V[1][j] + v2 * V[2][j];
            V[1][j] -= tau * s;
            V[2][j] -= tau * v2 * s;
        }
    }
}

// ---------------------------------------------------------------------------
__device__ __forceinline__ unsigned long long warp_min64(unsigned long long k) {
    unsigned hi = (unsigned)(k >> 32), lo = (unsigned)k;
    unsigned mhi = __reduce_min_sync(0xffffffffu, hi);
    unsigned lo2 = (hi == mhi) ? lo : 0xffffffffu;
    unsigned mlo = __reduce_min_sync(0xffffffffu, lo2);
    return ((unsigned long long)mhi << 32) | mlo;
}

__device__ __forceinline__ unsigned f2u(float f) {
    int i = __float_as_int(f);
    return (i < 0) ? ~(unsigned)i : ((unsigned)i | 0x80000000u);
}

__global__ void setup_kernel(const float* __restrict__ pos,
                             const float* __restrict__ coef) {
    int i = blockIdx.x * blockDim.x + threadIdx.x;
    if (i < NP) {
        float x = pos[3 * i], y = pos[3 * i + 1], z = pos[3 * i + 2];
        g_posq[i] = make_float4(x, y, z, x * x + y * y + z * z);
    }
    if (i < COUT * NG) {
        int t = i >> 7;
        int rem = i & 127;
        int o = rem >> 2, m2 = rem & 3;
        g_coefT[i] = coef[o * NG + t * 4 + m2];
    }
}

// ---------------------------------------------------------------------------
// Kernel 1: exact kNN (R12-R14 version — unchanged)
// ---------------------------------------------------------------------------
__global__ __launch_bounds__(256)
void knn_kernel() {
    const int tid = threadIdx.x;
    const int lane = tid & 31;
    const int wid = tid >> 5;
    const int qbase = blockIdx.x * QB;

    __shared__ unsigned long long s_surv[QB][SCAP];
    __shared__ unsigned s_b4[QB][8];
    __shared__ int s_cnt[QB];

    if (tid < QB) s_cnt[tid] = 0;

    float4 pq[QB];
#pragma unroll
    for (int q = 0; q < QB; ++q) pq[q] = g_posq[qbase + q];

    float mn[QB];
#pragma unroll
    for (int q = 0; q < QB; ++q) mn[q] = __int_as_float(0x7f800000);

#pragma unroll 4
    for (int j = 0; j < 16; ++j) {
        int cand = tid + (j << 8);
        float4 cq = g_posq[cand];
#pragma unroll
        for (int q = 0; q < QB; ++q) {
            float dot = pq[q].x * cq.x + pq[q].y * cq.y + pq[q].z * cq.z;
            float d2 = (pq[q].w + cq.w) - 2.f * dot;
            mn[q] = fminf(mn[q], d2);
        }
    }

#pragma unroll
    for (int q = 0; q < QB; ++q) {
        unsigned h = f2u(mn[q]), w4 = 0;
#pragma unroll
        for (int r = 0; r < 4; ++r) {
            w4 = __reduce_min_sync(0xffffffffu, h);
            if (h == w4) h = 0xffffffffu;
        }
        if (lane == 0) s_b4[q][wid] = w4;
    }
    __syncthreads();

    float Bf[QB];
#pragma unroll
    for (int q = 0; q < QB; ++q) {
        unsigned B = s_b4[q][0];
#pragma unroll
        for (int w = 1; w < 8; ++w) B = max(B, s_b4[q][w]);
        int bi = (B & 0x80000000u) ? (int)(B & 0x7fffffffu) : (int)~B;
        Bf[q] = __int_as_float(bi);
    }

#pragma unroll
    for (int q = 0; q < QB; ++q) {
        if (mn[q] <= Bf[q]) {
#pragma unroll 4
            for (int j = 0; j < 16; ++j) {
                int cand = tid + (j << 8);
                float4 cq = g_posq[cand];
                float dot = pq[q].x * cq.x + pq[q].y * cq.y + pq[q].z * cq.z;
                float d2 = (pq[q].w + cq.w) - 2.f * dot;
                if (d2 <= Bf[q]) {
                    unsigned u = f2u(d2);
                    int pos = atomicAdd(&s_cnt[q], 1);
                    if (pos < SCAP)
                        s_surv[q][pos] = ((unsigned long long)u << 32) | (unsigned)cand;
                }
            }
        }
    }
    __syncthreads();

    {
        const int q = wid;
        int S = s_cnt[q] < SCAP ? s_cnt[q] : SCAP;
        if (S <= 256) {
            unsigned long long k0, k1, k2, k3, k4, k5, k6, k7;
            k0 = (lane        < S) ? s_surv[q][lane]        : ~0ULL;
            k1 = (lane +  32  < S) ? s_surv[q][lane +  32]  : ~0ULL;
            k2 = (lane +  64  < S) ? s_surv[q][lane +  64]  : ~0ULL;
            k3 = (lane +  96  < S) ? s_surv[q][lane +  96]  : ~0ULL;
            k4 = (lane + 128  < S) ? s_surv[q][lane + 128]  : ~0ULL;
            k5 = (lane + 160  < S) ? s_surv[q][lane + 160]  : ~0ULL;
            k6 = (lane + 192  < S) ? s_surv[q][lane + 192]  : ~0ULL;
            k7 = (lane + 224  < S) ? s_surv[q][lane + 224]  : ~0ULL;
#define CE(a, b) { if (a > b) { unsigned long long t = a; a = b; b = t; } }
            CE(k0, k1) CE(k2, k3) CE(k4, k5) CE(k6, k7)
            CE(k0, k2) CE(k1, k3) CE(k1, k2)
            CE(k4, k6) CE(k5, k7) CE(k5, k6)
            CE(k0, k4) CE(k1, k5) CE(k2, k6) CE(k3, k7)
            CE(k2, k4) CE(k3, k5)
            CE(k1, k2) CE(k3, k4) CE(k5, k6)
#undef CE
#pragma unroll
            for (int r = 0; r < KNN; ++r) {
                unsigned long long w = warp_min64(k0);
                if (lane == 0) g_nbr[(qbase + q) * KNN + r] = (int)(w & 0xffffffffu);
                if (k0 == w) {
                    k0 = k1; k1 = k2; k2 = k3; k3 = k4;
                    k4 = k5; k5 = k6; k6 = k7; k7 = ~0ULL;
                }
            }
        } else {
            for (int r = 0; r < KNN; ++r) {
                unsigned long long m = ~0ULL; int mi = -1;
                for (int i = lane; i < S; i += 32) {
                    unsigned long long v = s_surv[q][i];
                    if (v < m) { m = v; mi = i; }
                }
                unsigned long long w = warp_min64(m);
                if (m == w && mi >= 0) s_surv[q][mi] = ~0ULL;
                if (lane == 0) g_nbr[(qbase + q) * KNN + r] = (int)(w & 0xffffffffu);
            }
        }
    }
}

// ---------------------------------------------------------------------------
// Kernel 2: frames — one warp per point (R13/R14 version — unchanged)
// ---------------------------------------------------------------------------
__global__ __launch_bounds__(128)
void frame_kernel(float* __restrict__ centers_out) {
    const int tid = threadIdx.x;
    const int lane = tid & 31;
    const int wid = tid >> 5;
    const int p = blockIdx.x * 4 + wid;

    const int nb = g_nbr[p * KNN + lane];
    const float4 q = g_posq[nb];

    float cx = q.x, cy = q.y, cz = q.z;
#pragma unroll
    for (int off = 16; off; off >>= 1) {
        cx += __shfl_xor_sync(0xffffffffu, cx, off);
        cy += __shfl_xor_sync(0xffffffffu, cy, off);
        cz += __shfl_xor_sync(0xffffffffu, cz, off);
    }
    cx *= 0.03125f; cy *= 0.03125f; cz *= 0.03125f;
    if (lane == 0) {
        centers_out[3 * p]     = cx;
        centers_out[3 * p + 1] = cy;
        centers_out[3 * p + 2] = cz;
    }

    const float lx = q.x - cx, ly = q.y - cy, lz = q.z - cz;
    float c00 = lx * lx, c01 = lx * ly, c02 = lx * lz;
    float c11 = ly * ly, c12 = ly * lz, c22 = lz * lz;
#pragma unroll
    for (int off = 16; off; off >>= 1) {
        c00 += __shfl_xor_sync(0xffffffffu, c00, off);
        c01 += __shfl_xor_sync(0xffffffffu, c01, off);
        c02 += __shfl_xor_sync(0xffffffffu, c02, off);
        c11 += __shfl_xor_sync(0xffffffffu, c11, off);
        c12 += __shfl_xor_sync(0xffffffffu, c12, off);
        c22 += __shfl_xor_sync(0xffffffffu, c22, off);
    }
    if (lane == 0) {
        float A[6] = {c00 * 0.03125f, c01 * 0.03125f, c02 * 0.03125f,
                      c11 * 0.03125f, c12 * 0.03125f, c22 * 0.03125f};
        float V[3][3];
        eigh3(A, V);
        g_frame[p * 3 + 0] = make_float4(cx, cy, cz, V[0][0]);
        g_frame[p * 3 + 1] = make_float4(V[0][1], V[0][2], V[1][0], V[1][1]);
        g_frame[p * 3 + 2] = make_float4(V[1][2], V[2][0], V[2][1], V[2][2]);
    }
}

// ---------------------------------------------------------------------------
// Kernel 3: conv — R14 structure + de-branched phase 4 (uniform 4xLDS.128;
// half1's extra products land in discarded accumulators — stored values
// bit-identical to R14).
// ---------------------------------------------------------------------------
__global__ __launch_bounds__(128, 7)
void conv_kernel(const float* __restrict__ chan,
                 float* __restrict__ out) {
    const int tid = threadIdx.x;
    const int lane = tid & 31;
    const int wid = tid >> 5;
    const int p = blockIdx.x * 4 + wid;

    __shared__ float s_basis[4][900];     // 32 rows x 28 floats + 4-float pad
    __shared__ float s_G[4][432];
    __shared__ float s_feat[4][32][16];   // dead after phase A; re-used as s_po

    const int nb = g_nbr[p * KNN + lane];
    const float4 q = g_posq[nb];

    {
        const float4* fr = (const float4*)(chan + nb * CIN);
        float4 f0 = fr[0], f1 = fr[1], f2 = fr[2], f3 = fr[3];
        float4* sf = (float4*)&s_feat[wid][lane][0];
        sf[0] = f0; sf[1] = f1; sf[2] = f2; sf[3] = f3;
    }

    const float4 f0 = __ldg(&g_frame[p * 3 + 0]);
    const float4 f1 = __ldg(&g_frame[p * 3 + 1]);
    const float4 f2 = __ldg(&g_frame[p * 3 + 2]);
    const float cx = f0.x, cy = f0.y, cz = f0.z;
    const float v00 = f0.w, v01 = f1.x, v02 = f1.y;
    const float v10 = f1.z, v11 = f1.w, v12 = f2.x;
    const float v20 = f2.y, v21 = f2.z, v22 = f2.w;

    const float lx = q.x - cx, ly = q.y - cy, lz = q.z - cz;

    {
        float x = lx * v00 + ly * v10 + lz * v20;
        float y = lx * v01 + ly * v11 + lz * v21;
        float z = lx * v02 + ly * v12 + lz * v22;
        float r = sqrtf(x * x + y * y + z * z);
        float ct = z / (r + 1e-8f);
        ct = fminf(fmaxf(ct, -1.f + 1e-6f), 1.f - 1e-6f);
        float theta = acosf(ct);
        float phi = atan2f(y, x);
        float rb[3] = {1.f, r, r * r};
        float tb[3] = {1.f, cosf(theta), cosf(2.f * theta)};
        float pb[3] = {1.f, cosf(phi), cosf(2.f * phi)};
        float* row = &s_basis[wid][lane * 28];
#pragma unroll
        for (int n = 0; n < 3; ++n)
#pragma unroll
            for (int l = 0; l < 3; ++l)
#pragma unroll
                for (int m = 0; m < 3; ++m)
                    row[n * 9 + l * 3 + m] = (rb[n] * tb[l]) * pb[m];
        row[27] = 0.f;
    }
    if (lane < 4) s_basis[wid][896 + lane] = 0.f;    // tail pad (k=31 overflow)
    __syncwarp();

    // phase 4 (de-branched): both halves issue the same 4 float4 loads;
    // half1's acc[11..15] take garbage products but are never stored.
    {
        const int c = lane >> 1;
        const int half = lane & 1;
        const int boff = half << 4;
        float acc[16];
#pragma unroll
        for (int i = 0; i < 16; ++i) acc[i] = 0.f;

#pragma unroll 8
        for (int k = 0; k < KNN; ++k) {
            float fv = s_feat[wid][k][c];
            const float* row = &s_basis[wid][k * 28 + boff];
            float4 b0 = *(const float4*)(row);
            float4 b1 = *(const float4*)(row + 4);
            float4 b2 = *(const float4*)(row + 8);
            float4 b3 = *(const float4*)(row + 12);
            acc[0]  += b0.x * fv; acc[1]  += b0.y * fv; acc[2]  += b0.z * fv; acc[3]  += b0.w * fv;
            acc[4]  += b1.x * fv; acc[5]  += b1.y * fv; acc[6]  += b1.z * fv; acc[7]  += b1.w * fv;
            acc[8]  += b2.x * fv; acc[9]  += b2.y * fv; acc[10] += b2.z * fv; acc[11] += b2.w * fv;
            acc[12] += b3.x * fv; acc[13] += b3.y * fv; acc[14] += b3.z * fv; acc[15] += b3.w * fv;
        }
        if (half == 0) {
#pragma unroll
            for (int i = 0; i < 16; ++i) s_G[wid][c * 27 + i] = acc[i];
        } else {
#pragma unroll
            for (int i = 0; i < 11; ++i) s_G[wid][c * 27 + 16 + i] = acc[i];
        }
    }
    __syncthreads();    // all 4 points' G ready; s_feat now dead

    // phase 5 (coef-amortized, R14): warp `wid` -> t-chunk [27*wid, 27*wid+27)
    float* s_po = &s_feat[0][0][0];
    {
        float a0 = 0.f, a1 = 0.f, a2 = 0.f, a3 = 0.f;
        const float* gT = g_coefT + lane * 4;
        const int t0 = 27 * wid;
#pragma unroll 9
        for (int t = t0; t < t0 + 27; ++t) {
            float4 cf = *(const float4*)(gT + t * 128);
            float4 g0 = *(const float4*)(&s_G[0][t * 4]);
            float4 g1 = *(const float4*)(&s_G[1][t * 4]);
            float4 g2 = *(const float4*)(&s_G[2][t * 4]);
            float4 g3 = *(const float4*)(&s_G[3][t * 4]);
            a0 += cf.x * g0.x; a0 += cf.y * g0.y; a0 += cf.z * g0.z; a0 += cf.w * g0.w;
            a1 += cf.x * g1.x; a1 += cf.y * g1.y; a1 += cf.z * g1.z; a1 += cf.w * g1.w;
            a2 += cf.x * g2.x; a2 += cf.y * g2.y; a2 += cf.z * g2.z; a2 += cf.w * g2.w;
            a3 += cf.x * g3.x; a3 += cf.y * g3.y; a3 += cf.z * g3.z; a3 += cf.w * g3.w;
        }
        s_po[(wid * 4 + 0) * 32 + lane] = a0;
        s_po[(wid * 4 + 1) * 32 + lane] = a1;
        s_po[(wid * 4 + 2) * 32 + lane] = a2;
        s_po[(wid * 4 + 3) * 32 + lane] = a3;
    }
    __syncthreads();

    {
        float r0 = s_po[(0 * 4 + wid) * 32 + lane];
        float r1 = s_po[(1 * 4 + wid) * 32 + lane];
        float r2 = s_po[(2 * 4 + wid) * 32 + lane];
        float r3 = s_po[(3 * 4 + wid) * 32 + lane];
        out[p * COUT + lane] = (r0 + r1) + (r2 + r3);
    }
}

extern "C" void kernel_launch(void* const* d_in, const int* in_sizes, int n_in,
                              void* d_out, int out_size) {
    const float* pos  = (const float*)d_in[0];
    const float* chan = (const float*)d_in[1];
    const float* coef = (const float*)d_in[3];

    float* d_outf = (float*)d_out;
    float* centers_ptr;
    float* out_ptr;
    if (out_size == NP * 3 + NP * COUT) {
        centers_ptr = d_outf;
        out_ptr     = d_outf + NP * 3;
    } else if (out_size == NP * COUT) {
        cudaGetSymbolAddress((void**)&centers_ptr, g_cscratch);
        out_ptr = d_outf;
    } else {
        centers_ptr = d_outf;
        cudaGetSymbolAddress((void**)&out_ptr, g_oscratch);
    }

    setup_kernel<<<54, 256>>>(pos, coef);
    knn_kernel<<<NP / QB, 256>>>();
    frame_kernel<<<NP / 4, 128>>>(centers_ptr);
    conv_kernel<<<NP / 4, 128>>>(chan, out_ptr);
}